// round 11
// baseline (speedup 1.0000x reference)
#include <cuda_runtime.h>
#include <math.h>
#include <stdint.h>

#define B_ 2
#define S_ 2048
#define D_ 1024
#define H_ 16
#define DK_ 64
#define FF_ 4096
#define NEG_ (-1000000000.0f)

// ---------------- scratch buffers ----------------
__device__ float g_n1[(size_t)B_ * S_ * D_];    // tf32 bits
__device__ float g_q [(size_t)B_ * S_ * D_];    // fp32
__device__ float g_k [(size_t)B_ * S_ * D_];    // fp32
__device__ float g_v [(size_t)B_ * S_ * D_];    // fp32
__device__ float g_o [(size_t)B_ * S_ * D_];    // tf32 bits
__device__ float g_x1[(size_t)B_ * S_ * D_];    // fp32
__device__ float g_n2[(size_t)B_ * S_ * D_];    // tf32 bits
__device__ float g_ff[(size_t)B_ * S_ * FF_];   // tf32 bits
__device__ uint32_t g_Wqc[(size_t)D_ * D_];
__device__ uint32_t g_Wkc[(size_t)D_ * D_];
__device__ uint32_t g_Wvc[(size_t)D_ * D_];
__device__ uint32_t g_Woc[(size_t)D_ * D_];
__device__ uint32_t g_W1c[(size_t)D_ * FF_];
__device__ uint32_t g_W2c[(size_t)FF_ * D_];

__device__ __forceinline__ uint32_t f2tf32(float f) {
    uint32_t r; asm("cvt.rna.tf32.f32 %0, %1;" : "=r"(r) : "f"(f)); return r;
}
__device__ __forceinline__ uint32_t smem_u32(const void* p) {
    uint32_t a;
    asm("{ .reg .u64 t; cvta.to.shared.u64 t, %1; cvt.u32.u64 %0, t; }" : "=r"(a) : "l"(p));
    return a;
}
#define CP_ASYNC16(dst, src) \
    asm volatile("cp.async.ca.shared.global [%0], [%1], 16;" :: "r"(dst), "l"(src) : "memory")
#define CP_ASYNC4(dst, src) \
    asm volatile("cp.async.ca.shared.global [%0], [%1], 4;" :: "r"(dst), "l"(src) : "memory")
#define CP_COMMIT() asm volatile("cp.async.commit_group;" ::: "memory")
#define CP_WAIT1() asm volatile("cp.async.wait_group 1;" ::: "memory")
#define CP_WAIT0() asm volatile("cp.async.wait_group 0;" ::: "memory")

__device__ __forceinline__ void mma_tf32(float c[4], const uint32_t a[4], const uint32_t b[2]) {
    asm volatile(
        "mma.sync.aligned.m16n8k8.row.col.f32.tf32.tf32.f32 "
        "{%0,%1,%2,%3}, {%4,%5,%6,%7}, {%8,%9}, {%0,%1,%2,%3};"
        : "+f"(c[0]), "+f"(c[1]), "+f"(c[2]), "+f"(c[3])
        : "r"(a[0]), "r"(a[1]), "r"(a[2]), "r"(a[3]), "r"(b[0]), "r"(b[1]));
}

// ---------------- weight pre-convert ----------------
__global__ __launch_bounds__(256) void cvtw_kernel(const float* __restrict__ in,
                                                   uint32_t* __restrict__ out)
{
    const int i = (blockIdx.x * 256 + threadIdx.x) * 4;
    const float4 v = *reinterpret_cast<const float4*>(in + i);
    uint4 u;
    u.x = f2tf32(v.x); u.y = f2tf32(v.y); u.z = f2tf32(v.z); u.w = f2tf32(v.w);
    *reinterpret_cast<uint4*>(out + i) = u;
}

// ================= tf32 tensor-core GEMM, 3-stage cp.async pipeline ===========
// C[M,N] = act(A[M,K] @ W[K,N] + bias) (+res); A,W tf32 bits, [M,K]/[K,N].
// A smem: row-major, 80B row stride (conflict-free LDS.32 fragment loads).
// B smem: fragment-packed (same layout as R8), filled by cp.async.4.
#define BM 128
#define BN 128
#define BK 16
#define A_STG 10240              // 128 rows * 80B
#define B_STG 8192
#define STG   (A_STG + B_STG)    // 18432
#define GEMM_SMEM (3 * STG)      // 55296

__global__ __launch_bounds__(256) void mmagemm_kernel(const uint32_t* __restrict__ A,
                                                      const uint32_t* __restrict__ W,
                                                      const float* __restrict__ bias,
                                                      const float* __restrict__ res,
                                                      float* __restrict__ C,
                                                      int M, int N, int K, int act, int outtf)
{
    extern __shared__ char sm[];
    const uint32_t sbase = smem_u32(sm);

    const int tid = threadIdx.x;
    const int wid = tid >> 5, lane = tid & 31;
    const int row0 = blockIdx.y * BM;
    const int col0 = blockIdx.x * BN;

    const int m0w = (wid >> 2) * 64;
    const int n0w = (wid & 3) * 32;
    const int bg8 = n0w >> 3;

    // ---- A loader: thread -> rows (ar, ar+64), 16B at byte col ac4
    const int ar = tid >> 2;
    const int acw = (tid & 3) << 2;          // word col 0,4,8,12
    const uint32_t adst0 = (uint32_t)(ar * 80 + acw * 4);
    const uint32_t adst1 = (uint32_t)((ar + 64) * 80 + acw * 4);

    // ---- B loader: thread -> n in {nn, nn+64}, k rows kq + s*4 (s=0..3)
    const int kq = tid >> 6;
    const int nn = tid & 63;
    uint32_t bdst[2][4];
#pragma unroll
    for (int t = 0; t < 2; t++) {
        const int nv = nn + t * 64;
        const int g8 = nv >> 3;
        const int slot = (((nv & 7) * 4 + kq) ^ (g8 & 3));
#pragma unroll
        for (int s = 0; s < 4; s++)
            bdst[t][s] = (uint32_t)(A_STG + (((s >> 1) * 16 + g8) << 8) + slot * 8 + (s & 1) * 4);
    }

    // ---- fragment addressing
    const int lg = lane >> 2, lt = lane & 3;
    const uint32_t afrag = (uint32_t)(lg * 80 + lt * 4);

    float acc[4][4][4];
#pragma unroll
    for (int mi = 0; mi < 4; mi++)
#pragma unroll
        for (int ni = 0; ni < 4; ni++)
#pragma unroll
            for (int r = 0; r < 4; r++) acc[mi][ni][r] = 0.f;

    const int NC = K / BK;

    // chunk loader
    auto load_chunk = [&](int k0, int st) {
        const uint32_t sb = sbase + (uint32_t)(st * STG);
        CP_ASYNC16(sb + adst0, A + (size_t)(row0 + ar) * K + k0 + acw);
        CP_ASYNC16(sb + adst1, A + (size_t)(row0 + 64 + ar) * K + k0 + acw);
#pragma unroll
        for (int t = 0; t < 2; t++)
#pragma unroll
            for (int s = 0; s < 4; s++)
                CP_ASYNC4(sb + bdst[t][s],
                          W + (size_t)(k0 + kq + s * 4) * N + col0 + nn + t * 64);
    };

    load_chunk(0, 0);  CP_COMMIT();
    load_chunk(BK, 1); CP_COMMIT();

    for (int c = 0; c < NC; c++) {
        if (c + 2 < NC) { CP_WAIT1(); } else { CP_WAIT0(); }
        __syncthreads();
        if (c + 2 < NC) { load_chunk((c + 2) * BK, (c + 2) % 3); CP_COMMIT(); }

        const int st = c % 3;
        const char* Ab = sm + st * STG;
        const char* Bb = Ab + A_STG;
#pragma unroll
        for (int kb = 0; kb < 2; kb++) {
            uint32_t afr[4][4];
            uint2 bfr[4];
#pragma unroll
            for (int mi = 0; mi < 4; mi++) {
                const char* base = Ab + (m0w + mi * 16) * 80 + afrag + kb * 32;
                afr[mi][0] = *reinterpret_cast<const uint32_t*>(base);
                afr[mi][1] = *reinterpret_cast<const uint32_t*>(base + 640);
                afr[mi][2] = *reinterpret_cast<const uint32_t*>(base + 16);
                afr[mi][3] = *reinterpret_cast<const uint32_t*>(base + 656);
            }
#pragma unroll
            for (int ni = 0; ni < 4; ni++) {
                const int g8 = bg8 + ni;
                bfr[ni] = *reinterpret_cast<const uint2*>(Bb + ((kb * 16 + g8) << 8) +
                                                          ((lane ^ (g8 & 3)) << 3));
            }
#pragma unroll
            for (int mi = 0; mi < 4; mi++)
#pragma unroll
                for (int ni = 0; ni < 4; ni++)
                    mma_tf32(acc[mi][ni], afr[mi],
                             reinterpret_cast<const uint32_t*>(&bfr[ni]));
        }
    }

    // epilogue
#pragma unroll
    for (int mi = 0; mi < 4; mi++) {
#pragma unroll
        for (int half = 0; half < 2; half++) {
            const int r = row0 + m0w + mi * 16 + lg + half * 8;
#pragma unroll
            for (int ni = 0; ni < 4; ni++) {
                const int cc = col0 + n0w + ni * 8 + lt * 2;
                float2 o;
                o.x = acc[mi][ni][half * 2 + 0] + bias[cc];
                o.y = acc[mi][ni][half * 2 + 1] + bias[cc + 1];
                if (act == 1) {
                    o.x = 0.5f * o.x * (1.0f + erff(o.x * 0.70710678118654752f));
                    o.y = 0.5f * o.y * (1.0f + erff(o.y * 0.70710678118654752f));
                }
                if (res) {
                    const float2 rv = *reinterpret_cast<const float2*>(res + (size_t)r * N + cc);
                    o.x += rv.x; o.y += rv.y;
                }
                if (outtf) {
                    o.x = __uint_as_float(f2tf32(o.x));
                    o.y = __uint_as_float(f2tf32(o.y));
                }
                *reinterpret_cast<float2*>(C + (size_t)r * N + cc) = o;
            }
        }
    }
}

// ---------------- LayerNorm (emits tf32 bits) ----------------
__global__ __launch_bounds__(256) void ln_kernel(const float* __restrict__ x,
                                                 const float* __restrict__ g,
                                                 const float* __restrict__ b,
                                                 float* __restrict__ out)
{
    const int row = blockIdx.x;
    const float* xr = x + (size_t)row * D_;
    float* outr = out + (size_t)row * D_;
    const int tid = threadIdx.x;

    float4 v = reinterpret_cast<const float4*>(xr)[tid];
    float s = v.x + v.y + v.z + v.w;
    float ss = v.x * v.x + v.y * v.y + v.z * v.z + v.w * v.w;

    __shared__ float sh_s[8], sh_ss[8];
    for (int off = 16; off; off >>= 1) {
        s  += __shfl_xor_sync(0xffffffffu, s, off);
        ss += __shfl_xor_sync(0xffffffffu, ss, off);
    }
    const int wid = tid >> 5, lane = tid & 31;
    if (lane == 0) { sh_s[wid] = s; sh_ss[wid] = ss; }
    __syncthreads();
    if (wid == 0) {
        s  = (lane < 8) ? sh_s[lane]  : 0.f;
        ss = (lane < 8) ? sh_ss[lane] : 0.f;
        for (int off = 4; off; off >>= 1) {
            s  += __shfl_xor_sync(0xffffffffu, s, off);
            ss += __shfl_xor_sync(0xffffffffu, ss, off);
        }
        if (lane == 0) { sh_s[0] = s; sh_ss[0] = ss; }
    }
    __syncthreads();
    const float mu = sh_s[0] * (1.0f / D_);
    const float var = sh_ss[0] * (1.0f / D_) - mu * mu;
    const float rstd = rsqrtf(var + 1e-5f);

    float4 gv = reinterpret_cast<const float4*>(g)[tid];
    float4 bv = reinterpret_cast<const float4*>(b)[tid];
    uint4 o;
    o.x = f2tf32((v.x - mu) * rstd * gv.x + bv.x);
    o.y = f2tf32((v.y - mu) * rstd * gv.y + bv.y);
    o.z = f2tf32((v.z - mu) * rstd * gv.z + bv.z);
    o.w = f2tf32((v.w - mu) * rstd * gv.w + bv.w);
    reinterpret_cast<uint4*>(outr)[tid] = o;
}

// ================= sparse attention v3 (R8 version) =================
#define QB 64
#define KW 192
#define KP 68
#define VP 196
#define ATTN_SMEM ((KW * KP + 64 * VP + 8 * 32) * 4)

__global__ __launch_bounds__(256) void attn3_kernel(const float* __restrict__ Q,
                                                    const float* __restrict__ K,
                                                    const float* __restrict__ V,
                                                    const int* __restrict__ mask,
                                                    float* __restrict__ O)
{
    extern __shared__ float smattn[];
    float* Ks  = smattn;
    float* Vt  = smattn + KW * KP;
    float* psm = smattn + KW * KP + 64 * VP;

    const int qb0 = blockIdx.x * QB;
    const int h = blockIdx.y;
    const int b = blockIdx.z;
    const int tid = threadIdx.x;
    const int warp = tid >> 5, lane = tid & 31;
    const int base_row = qb0 - 128;

    for (int idx = tid; idx < KW * 64; idx += 256) {
        const int r = idx >> 6, d = idx & 63;
        const int j = base_row + r;
        float kv = 0.f, vv = 0.f;
        if (j >= 0) {
            const size_t g = ((size_t)(b * S_ + j)) * D_ + h * 64 + d;
            kv = K[g]; vv = V[g];
        }
        Ks[r * KP + d] = kv;
        Vt[d * VP + r] = vv;
    }
    __syncthreads();

    float* pb = psm + warp * 32;

#pragma unroll 1
    for (int qi = 0; qi < 8; qi++) {
        const int i = qb0 + warp * 8 + qi;
        const int o_in_blk = warp * 8 + qi;
        const float4* q4 = reinterpret_cast<const float4*>(Q + ((size_t)(b * S_ + i)) * D_ + h * 64);
        float4 rq[16];
#pragma unroll
        for (int d = 0; d < 16; d++) rq[d] = __ldg(q4 + d);
        const int* mrow = mask + (size_t)i * S_;

        float m = -INFINITY, l = 0.f, acc0 = 0.f, acc1 = 0.f;

        // strided keys
        {
            const int j = i - 256 - 128 * lane;
            float s = -INFINITY;
            if (j >= 0) {
                const float4* kr = reinterpret_cast<const float4*>(K + ((size_t)(b * S_ + j)) * D_ + h * 64);
                float dv = 0.f;
#pragma unroll
                for (int d = 0; d < 16; d++) {
                    const float4 kv = __ldg(kr + d);
                    dv = fmaf(rq[d].x, kv.x, dv);
                    dv = fmaf(rq[d].y, kv.y, dv);
                    dv = fmaf(rq[d].z, kv.z, dv);
                    dv = fmaf(rq[d].w, kv.w, dv);
                }
                s = dv * 0.125f;
                if (mrow[j] == 0) s = NEG_;
            }
            float bm = s;
            for (int off = 16; off; off >>= 1)
                bm = fmaxf(bm, __shfl_xor_sync(0xffffffffu, bm, off));
            if (bm > -1e37f) {
                const float nm = fmaxf(m, bm);
                const float sc = __expf(m - nm);
                const float p = __expf(s - nm);
                float bs = p;
                for (int off = 16; off; off >>= 1)
                    bs += __shfl_xor_sync(0xffffffffu, bs, off);
                l = l * sc + bs;
                acc0 *= sc; acc1 *= sc;
                m = nm;
                const int cnt = (i - 256) / 128 + 1;
                for (int l2 = 0; l2 < cnt; l2++) {
                    const float pv = __shfl_sync(0xffffffffu, p, l2);
                    const int j2 = i - 256 - 128 * l2;
                    const float* vr = V + ((size_t)(b * S_ + j2)) * D_ + h * 64;
                    acc0 = fmaf(pv, __ldg(vr + lane), acc0);
                    acc1 = fmaf(pv, __ldg(vr + lane + 32), acc1);
                }
            }
        }

        // local window: 5 aligned 32-key segments
        const int u0 = o_in_blk >> 5;
#pragma unroll 1
        for (int t = 0; t < 5; t++) {
            const int koff = (u0 + t) * 32;
            const int j = base_row + koff + lane;
            float s = -INFINITY;
            if (j >= 0 && j >= i - 128 && j <= i) {
                const float4* kr = reinterpret_cast<const float4*>(Ks + (koff + lane) * KP);
                float dv = 0.f;
#pragma unroll
                for (int d = 0; d < 16; d++) {
                    const float4 kv = kr[d];
                    dv = fmaf(rq[d].x, kv.x, dv);
                    dv = fmaf(rq[d].y, kv.y, dv);
                    dv = fmaf(rq[d].z, kv.z, dv);
                    dv = fmaf(rq[d].w, kv.w, dv);
                }
                s = dv * 0.125f;
                if (mrow[j] == 0) s = NEG_;
            }
            float bm = s;
            for (int off = 16; off; off >>= 1)
                bm = fmaxf(bm, __shfl_xor_sync(0xffffffffu, bm, off));
            if (bm > -1e37f) {
                const float nm = fmaxf(m, bm);
                const float sc = __expf(m - nm);
                const float p = __expf(s - nm);
                float bs = p;
                for (int off = 16; off; off >>= 1)
                    bs += __shfl_xor_sync(0xffffffffu, bs, off);
                l = l * sc + bs;
                acc0 *= sc; acc1 *= sc;
                m = nm;

                __syncwarp();
                pb[lane] = p;
                __syncwarp();
                const float4* pv4 = reinterpret_cast<const float4*>(pb);
                const float4* v0 = reinterpret_cast<const float4*>(Vt + lane * VP + koff);
                const float4* v1 = reinterpret_cast<const float4*>(Vt + (lane + 32) * VP + koff);
#pragma unroll
                for (int kk = 0; kk < 8; kk++) {
                    const float4 pp = pv4[kk];
                    const float4 va = v0[kk];
                    const float4 vb = v1[kk];
                    acc0 = fmaf(pp.x, va.x, acc0);
                    acc0 = fmaf(pp.y, va.y, acc0);
                    acc0 = fmaf(pp.z, va.z, acc0);
                    acc0 = fmaf(pp.w, va.w, acc0);
                    acc1 = fmaf(pp.x, vb.x, acc1);
                    acc1 = fmaf(pp.y, vb.y, acc1);
                    acc1 = fmaf(pp.z, vb.z, acc1);
                    acc1 = fmaf(pp.w, vb.w, acc1);
                }
            }
        }

        const float inv = 1.0f / l;
        float* orow = O + ((size_t)(b * S_ + i)) * D_ + h * 64;
        orow[lane]      = __uint_as_float(f2tf32(acc0 * inv));
        orow[lane + 32] = __uint_as_float(f2tf32(acc1 * inv));
    }
}

// ---------------- host launcher ----------------
extern "C" void kernel_launch(void* const* d_in, const int* in_sizes, int n_in,
                              void* d_out, int out_size)
{
    (void)in_sizes; (void)n_in; (void)out_size;
    const float* x    = (const float*)d_in[0];
    const int*   mask = (const int*)  d_in[1];
    const float* Wq = (const float*)d_in[2];  const float* bq = (const float*)d_in[3];
    const float* Wk = (const float*)d_in[4];  const float* bk = (const float*)d_in[5];
    const float* Wv = (const float*)d_in[6];  const float* bv = (const float*)d_in[7];
    const float* Wo = (const float*)d_in[8];  const float* bo = (const float*)d_in[9];
    const float* W1 = (const float*)d_in[10]; const float* bf1 = (const float*)d_in[11];
    const float* W2 = (const float*)d_in[12]; const float* bf2 = (const float*)d_in[13];
    const float* g1 = (const float*)d_in[14]; const float* bl1 = (const float*)d_in[15];
    const float* g2 = (const float*)d_in[16]; const float* bl2 = (const float*)d_in[17];
    float* out = (float*)d_out;

    float *n1, *q, *k, *v, *o, *x1, *n2, *ff;
    uint32_t *Wqc, *Wkc, *Wvc, *Woc, *W1c, *W2c;
    cudaGetSymbolAddress((void**)&n1, g_n1);
    cudaGetSymbolAddress((void**)&q,  g_q);
    cudaGetSymbolAddress((void**)&k,  g_k);
    cudaGetSymbolAddress((void**)&v,  g_v);
    cudaGetSymbolAddress((void**)&o,  g_o);
    cudaGetSymbolAddress((void**)&x1, g_x1);
    cudaGetSymbolAddress((void**)&n2, g_n2);
    cudaGetSymbolAddress((void**)&ff, g_ff);
    cudaGetSymbolAddress((void**)&Wqc, g_Wqc);
    cudaGetSymbolAddress((void**)&Wkc, g_Wkc);
    cudaGetSymbolAddress((void**)&Wvc, g_Wvc);
    cudaGetSymbolAddress((void**)&Woc, g_Woc);
    cudaGetSymbolAddress((void**)&W1c, g_W1c);
    cudaGetSymbolAddress((void**)&W2c, g_W2c);

    cudaFuncSetAttribute(mmagemm_kernel, cudaFuncAttributeMaxDynamicSharedMemorySize, GEMM_SMEM);
    cudaFuncSetAttribute(attn3_kernel, cudaFuncAttributeMaxDynamicSharedMemorySize, ATTN_SMEM);

    const int M = B_ * S_;  // 4096

    // 0) weight pre-convert to tf32 bits
    cvtw_kernel<<<(D_ * D_) / 1024, 256>>>(Wq, Wqc);
    cvtw_kernel<<<(D_ * D_) / 1024, 256>>>(Wk, Wkc);
    cvtw_kernel<<<(D_ * D_) / 1024, 256>>>(Wv, Wvc);
    cvtw_kernel<<<(D_ * D_) / 1024, 256>>>(Wo, Woc);
    cvtw_kernel<<<(D_ * FF_) / 1024, 256>>>(W1, W1c);
    cvtw_kernel<<<(FF_ * D_) / 1024, 256>>>(W2, W2c);

    // 1) LN1 -> n1 (tf32)
    ln_kernel<<<M, 256>>>(x, g1, bl1, n1);

    // 2) Q, K, V projections
    {
        dim3 grid(D_ / BN, M / BM);
        mmagemm_kernel<<<grid, 256, GEMM_SMEM>>>((const uint32_t*)n1, Wqc, bq, nullptr, q, M, D_, D_, 0, 0);
        mmagemm_kernel<<<grid, 256, GEMM_SMEM>>>((const uint32_t*)n1, Wkc, bk, nullptr, k, M, D_, D_, 0, 0);
        mmagemm_kernel<<<grid, 256, GEMM_SMEM>>>((const uint32_t*)n1, Wvc, bv, nullptr, v, M, D_, D_, 0, 0);
    }

    // 3) sparse attention -> o (tf32)
    {
        dim3 grid(S_ / QB, H_, B_);
        attn3_kernel<<<grid, 256, ATTN_SMEM>>>(q, k, v, mask, o);
    }

    // 4) output projection + residual -> x1 (fp32)
    {
        dim3 grid(D_ / BN, M / BM);
        mmagemm_kernel<<<grid, 256, GEMM_SMEM>>>((const uint32_t*)o, Woc, bo, x, x1, M, D_, D_, 0, 0);
    }

    // 5) LN2 -> n2 (tf32)
    ln_kernel<<<M, 256>>>(x1, g2, bl2, n2);

    // 6) FFN up + GELU -> ff (tf32)
    {
        dim3 grid(FF_ / BN, M / BM);
        mmagemm_kernel<<<grid, 256, GEMM_SMEM>>>((const uint32_t*)n2, W1c, bf1, nullptr, ff, M, FF_, D_, 1, 1);
    }

    // 7) FFN down + residual -> out (fp32)
    {
        dim3 grid(D_ / BN, M / BM);
        mmagemm_kernel<<<grid, 256, GEMM_SMEM>>>((const uint32_t*)ff, W2c, bf2, x1, out, M, D_, FF_, 0, 0);
    }
}

// round 12
// speedup vs baseline: 1.0326x; 1.0326x over previous
#include <cuda_runtime.h>
#include <math.h>
#include <stdint.h>

#define B_ 2
#define S_ 2048
#define D_ 1024
#define H_ 16
#define DK_ 64
#define FF_ 4096
#define NEG_ (-1000000000.0f)

// ---------------- scratch buffers ----------------
__device__ float g_n1[(size_t)B_ * S_ * D_];    // tf32 bits
__device__ float g_q [(size_t)B_ * S_ * D_];    // fp32
__device__ float g_k [(size_t)B_ * S_ * D_];    // fp32
__device__ float g_v [(size_t)B_ * S_ * D_];    // fp32
__device__ float g_o [(size_t)B_ * S_ * D_];    // tf32 bits
__device__ float g_x1[(size_t)B_ * S_ * D_];    // fp32
__device__ float g_n2[(size_t)B_ * S_ * D_];    // tf32 bits
__device__ float g_ff[(size_t)B_ * S_ * FF_];   // tf32 bits
__device__ uint32_t g_Wqc[(size_t)D_ * D_];
__device__ uint32_t g_Wkc[(size_t)D_ * D_];
__device__ uint32_t g_Wvc[(size_t)D_ * D_];
__device__ uint32_t g_Woc[(size_t)D_ * D_];
__device__ uint32_t g_W1c[(size_t)D_ * FF_];
__device__ uint32_t g_W2c[(size_t)FF_ * D_];

__device__ __forceinline__ uint32_t f2tf32(float f) {
    uint32_t r; asm("cvt.rna.tf32.f32 %0, %1;" : "=r"(r) : "f"(f)); return r;
}

__device__ __forceinline__ void mma_tf32(float c[4], const uint32_t a[4], const uint32_t b[2]) {
    asm volatile(
        "mma.sync.aligned.m16n8k8.row.col.f32.tf32.tf32.f32 "
        "{%0,%1,%2,%3}, {%4,%5,%6,%7}, {%8,%9}, {%0,%1,%2,%3};"
        : "+f"(c[0]), "+f"(c[1]), "+f"(c[2]), "+f"(c[3])
        : "r"(a[0]), "r"(a[1]), "r"(a[2]), "r"(a[3]), "r"(b[0]), "r"(b[1]));
}

// ---------------- weight pre-convert ----------------
__global__ __launch_bounds__(256) void cvtw_kernel(const float* __restrict__ in,
                                                   uint32_t* __restrict__ out)
{
    const int i = (blockIdx.x * 256 + threadIdx.x) * 4;
    const float4 v = *reinterpret_cast<const float4*>(in + i);
    uint4 u;
    u.x = f2tf32(v.x); u.y = f2tf32(v.y); u.z = f2tf32(v.z); u.w = f2tf32(v.w);
    *reinterpret_cast<uint4*>(out + i) = u;
}

// ================= tf32 tensor-core GEMM, 128x256 CTA tile ====================
// C[M,N] = act(A[M,K] @ W[K,N] + bias) (+res); A,W tf32 bits, [M,K]/[K,N].
// 8 warps, warp tile 64x64 (amortizes A-fragment smem reads over 2x flops).
// A smem layout identical to R8; B extended to 32 g8-groups per kb.
#define BM 128
#define BN 256
#define BK 16
#define ASZ 8192
#define BSZ 16384
#define GEMM_SMEM (2 * (ASZ + BSZ))   // 49152

__global__ __launch_bounds__(256) void mmagemm_kernel(const uint32_t* __restrict__ A,
                                                      const uint32_t* __restrict__ W,
                                                      const float* __restrict__ bias,
                                                      const float* __restrict__ res,
                                                      float* __restrict__ C,
                                                      int M, int N, int K, int act, int outtf)
{
    extern __shared__ char sm[];
    // layout: [A0][A1][B0][B1]
    const int tid = threadIdx.x;
    const int wid = tid >> 5, lane = tid & 31;
    const int row0 = blockIdx.y * BM;
    const int col0 = blockIdx.x * BN;

    const int m0w = (wid >> 2) * 64;
    const int n0w = (wid & 3) * 64;
    const int g16b = m0w >> 4;          // 0 or 4
    const int bg8 = n0w >> 3;           // 0,8,16,24

    // ---- A loader (R8-identical): rows (ar, ar+64), cols ac..ac+3
    const int ar = tid >> 2;
    const int ac = (tid & 3) << 2;
    const int lga = ar & 7;
    const int swa = (lga >> 1) & 3;
    const int abase = ((ac >> 3) * 8 + (ar >> 4)) * 512 +
                      ((((ac >> 2) & 1) * 2) + ((ar >> 3) & 1)) * 4;
    int aoff[4];
#pragma unroll
    for (int j = 0; j < 4; j++) aoff[j] = abase + (((lga * 4 + j) ^ swa) << 4);

    // ---- B loader: thread -> n in {nn, nn+64, nn+128, nn+192}, k rows kq+s*4
    const int kq = tid >> 6;
    const int nn = tid & 63;
    int boff[4][2];                      // [t][kb]
#pragma unroll
    for (int t = 0; t < 4; t++) {
        const int nv = nn + t * 64;
        const int g8 = nv >> 3;
        const int slot = (((nv & 7) * 4 + kq) ^ (g8 & 3));
#pragma unroll
        for (int kb = 0; kb < 2; kb++)
            boff[t][kb] = ((kb * 32 + g8) << 8) + slot * 8;
    }

    const int aslot = ((lane ^ ((lane >> 3) & 3)) << 4);

    float acc[4][8][4];
#pragma unroll
    for (int mi = 0; mi < 4; mi++)
#pragma unroll
        for (int ni = 0; ni < 8; ni++)
#pragma unroll
            for (int r = 0; r < 4; r++) acc[mi][ni][r] = 0.f;

    const int NC = K / BK;

    // prologue: chunk 0 -> buffer 0
    {
        char* Ab = sm;
        char* Bb = sm + 2 * ASZ;
        const uint4 av0 = *reinterpret_cast<const uint4*>(A + (size_t)(row0 + ar) * K + ac);
        const uint4 av1 = *reinterpret_cast<const uint4*>(A + (size_t)(row0 + 64 + ar) * K + ac);
        const uint32_t a0[4] = {av0.x, av0.y, av0.z, av0.w};
        const uint32_t a1[4] = {av1.x, av1.y, av1.z, av1.w};
#pragma unroll
        for (int j = 0; j < 4; j++) {
            *reinterpret_cast<uint32_t*>(Ab + aoff[j]) = a0[j];
            *reinterpret_cast<uint32_t*>(Ab + aoff[j] + 2048) = a1[j];
        }
        uint32_t wreg[4][4];
#pragma unroll
        for (int t = 0; t < 4; t++)
#pragma unroll
            for (int s = 0; s < 4; s++)
                wreg[t][s] = W[(size_t)(kq + s * 4) * N + col0 + nn + t * 64];
#pragma unroll
        for (int t = 0; t < 4; t++)
#pragma unroll
            for (int kb = 0; kb < 2; kb++) {
                uint2 u = {wreg[t][kb * 2 + 0], wreg[t][kb * 2 + 1]};
                *reinterpret_cast<uint2*>(Bb + boff[t][kb]) = u;
            }
    }
    __syncthreads();

    for (int c = 0; c < NC; c++) {
        const int buf = c & 1;
        const char* Ab = sm + buf * ASZ;
        const char* Bb = sm + 2 * ASZ + buf * BSZ;

        uint4 av0, av1;
        uint32_t wreg[4][4];
        if (c + 1 < NC) {
            const int k0 = (c + 1) * BK;
            av0 = *reinterpret_cast<const uint4*>(A + (size_t)(row0 + ar) * K + k0 + ac);
            av1 = *reinterpret_cast<const uint4*>(A + (size_t)(row0 + 64 + ar) * K + k0 + ac);
#pragma unroll
            for (int t = 0; t < 4; t++)
#pragma unroll
                for (int s = 0; s < 4; s++)
                    wreg[t][s] = W[(size_t)(k0 + kq + s * 4) * N + col0 + nn + t * 64];
        }

#pragma unroll
        for (int kb = 0; kb < 2; kb++) {
            const char* Abk = Ab + (kb << 12);
            const char* Bbk = Bb + (kb << 13);
            uint4 afr[4];
            uint2 bfr[8];
#pragma unroll
            for (int mi = 0; mi < 4; mi++)
                afr[mi] = *reinterpret_cast<const uint4*>(Abk + ((g16b + mi) << 9) + aslot);
#pragma unroll
            for (int ni = 0; ni < 8; ni++) {
                const int g8 = bg8 + ni;
                bfr[ni] = *reinterpret_cast<const uint2*>(Bbk + (g8 << 8) + ((lane ^ (g8 & 3)) << 3));
            }
#pragma unroll
            for (int mi = 0; mi < 4; mi++)
#pragma unroll
                for (int ni = 0; ni < 8; ni++)
                    mma_tf32(acc[mi][ni], reinterpret_cast<const uint32_t*>(&afr[mi]),
                             reinterpret_cast<const uint32_t*>(&bfr[ni]));
        }

        if (c + 1 < NC) {
            char* An = sm + (buf ^ 1) * ASZ;
            char* Bn = sm + 2 * ASZ + (buf ^ 1) * BSZ;
            const uint32_t a0[4] = {av0.x, av0.y, av0.z, av0.w};
            const uint32_t a1[4] = {av1.x, av1.y, av1.z, av1.w};
#pragma unroll
            for (int j = 0; j < 4; j++) {
                *reinterpret_cast<uint32_t*>(An + aoff[j]) = a0[j];
                *reinterpret_cast<uint32_t*>(An + aoff[j] + 2048) = a1[j];
            }
#pragma unroll
            for (int t = 0; t < 4; t++)
#pragma unroll
                for (int kb = 0; kb < 2; kb++) {
                    uint2 u = {wreg[t][kb * 2 + 0], wreg[t][kb * 2 + 1]};
                    *reinterpret_cast<uint2*>(Bn + boff[t][kb]) = u;
                }
            __syncthreads();
        }
    }

    // epilogue
    const int lg = lane >> 2, lt = lane & 3;
#pragma unroll
    for (int mi = 0; mi < 4; mi++) {
#pragma unroll
        for (int half = 0; half < 2; half++) {
            const int r = row0 + m0w + mi * 16 + lg + half * 8;
#pragma unroll
            for (int ni = 0; ni < 8; ni++) {
                const int cc = col0 + n0w + ni * 8 + lt * 2;
                float2 o;
                o.x = acc[mi][ni][half * 2 + 0] + bias[cc];
                o.y = acc[mi][ni][half * 2 + 1] + bias[cc + 1];
                if (act == 1) {
                    o.x = 0.5f * o.x * (1.0f + erff(o.x * 0.70710678118654752f));
                    o.y = 0.5f * o.y * (1.0f + erff(o.y * 0.70710678118654752f));
                }
                if (res) {
                    const float2 rv = *reinterpret_cast<const float2*>(res + (size_t)r * N + cc);
                    o.x += rv.x; o.y += rv.y;
                }
                if (outtf) {
                    o.x = __uint_as_float(f2tf32(o.x));
                    o.y = __uint_as_float(f2tf32(o.y));
                }
                *reinterpret_cast<float2*>(C + (size_t)r * N + cc) = o;
            }
        }
    }
}

// ---------------- LayerNorm (emits tf32 bits) ----------------
__global__ __launch_bounds__(256) void ln_kernel(const float* __restrict__ x,
                                                 const float* __restrict__ g,
                                                 const float* __restrict__ b,
                                                 float* __restrict__ out)
{
    const int row = blockIdx.x;
    const float* xr = x + (size_t)row * D_;
    float* outr = out + (size_t)row * D_;
    const int tid = threadIdx.x;

    float4 v = reinterpret_cast<const float4*>(xr)[tid];
    float s = v.x + v.y + v.z + v.w;
    float ss = v.x * v.x + v.y * v.y + v.z * v.z + v.w * v.w;

    __shared__ float sh_s[8], sh_ss[8];
    for (int off = 16; off; off >>= 1) {
        s  += __shfl_xor_sync(0xffffffffu, s, off);
        ss += __shfl_xor_sync(0xffffffffu, ss, off);
    }
    const int wid = tid >> 5, lane = tid & 31;
    if (lane == 0) { sh_s[wid] = s; sh_ss[wid] = ss; }
    __syncthreads();
    if (wid == 0) {
        s  = (lane < 8) ? sh_s[lane]  : 0.f;
        ss = (lane < 8) ? sh_ss[lane] : 0.f;
        for (int off = 4; off; off >>= 1) {
            s  += __shfl_xor_sync(0xffffffffu, s, off);
            ss += __shfl_xor_sync(0xffffffffu, ss, off);
        }
        if (lane == 0) { sh_s[0] = s; sh_ss[0] = ss; }
    }
    __syncthreads();
    const float mu = sh_s[0] * (1.0f / D_);
    const float var = sh_ss[0] * (1.0f / D_) - mu * mu;
    const float rstd = rsqrtf(var + 1e-5f);

    float4 gv = reinterpret_cast<const float4*>(g)[tid];
    float4 bv = reinterpret_cast<const float4*>(b)[tid];
    uint4 o;
    o.x = f2tf32((v.x - mu) * rstd * gv.x + bv.x);
    o.y = f2tf32((v.y - mu) * rstd * gv.y + bv.y);
    o.z = f2tf32((v.z - mu) * rstd * gv.z + bv.z);
    o.w = f2tf32((v.w - mu) * rstd * gv.w + bv.w);
    reinterpret_cast<uint4*>(outr)[tid] = o;
}

// ================= sparse attention v3 (R8 version) =================
#define QB 64
#define KW 192
#define KP 68
#define VP 196
#define ATTN_SMEM ((KW * KP + 64 * VP + 8 * 32) * 4)

__global__ __launch_bounds__(256) void attn3_kernel(const float* __restrict__ Q,
                                                    const float* __restrict__ K,
                                                    const float* __restrict__ V,
                                                    const int* __restrict__ mask,
                                                    float* __restrict__ O)
{
    extern __shared__ float smattn[];
    float* Ks  = smattn;
    float* Vt  = smattn + KW * KP;
    float* psm = smattn + KW * KP + 64 * VP;

    const int qb0 = blockIdx.x * QB;
    const int h = blockIdx.y;
    const int b = blockIdx.z;
    const int tid = threadIdx.x;
    const int warp = tid >> 5, lane = tid & 31;
    const int base_row = qb0 - 128;

    for (int idx = tid; idx < KW * 64; idx += 256) {
        const int r = idx >> 6, d = idx & 63;
        const int j = base_row + r;
        float kv = 0.f, vv = 0.f;
        if (j >= 0) {
            const size_t g = ((size_t)(b * S_ + j)) * D_ + h * 64 + d;
            kv = K[g]; vv = V[g];
        }
        Ks[r * KP + d] = kv;
        Vt[d * VP + r] = vv;
    }
    __syncthreads();

    float* pb = psm + warp * 32;

#pragma unroll 1
    for (int qi = 0; qi < 8; qi++) {
        const int i = qb0 + warp * 8 + qi;
        const int o_in_blk = warp * 8 + qi;
        const float4* q4 = reinterpret_cast<const float4*>(Q + ((size_t)(b * S_ + i)) * D_ + h * 64);
        float4 rq[16];
#pragma unroll
        for (int d = 0; d < 16; d++) rq[d] = __ldg(q4 + d);
        const int* mrow = mask + (size_t)i * S_;

        float m = -INFINITY, l = 0.f, acc0 = 0.f, acc1 = 0.f;

        // strided keys
        {
            const int j = i - 256 - 128 * lane;
            float s = -INFINITY;
            if (j >= 0) {
                const float4* kr = reinterpret_cast<const float4*>(K + ((size_t)(b * S_ + j)) * D_ + h * 64);
                float dv = 0.f;
#pragma unroll
                for (int d = 0; d < 16; d++) {
                    const float4 kv = __ldg(kr + d);
                    dv = fmaf(rq[d].x, kv.x, dv);
                    dv = fmaf(rq[d].y, kv.y, dv);
                    dv = fmaf(rq[d].z, kv.z, dv);
                    dv = fmaf(rq[d].w, kv.w, dv);
                }
                s = dv * 0.125f;
                if (mrow[j] == 0) s = NEG_;
            }
            float bm = s;
            for (int off = 16; off; off >>= 1)
                bm = fmaxf(bm, __shfl_xor_sync(0xffffffffu, bm, off));
            if (bm > -1e37f) {
                const float nm = fmaxf(m, bm);
                const float sc = __expf(m - nm);
                const float p = __expf(s - nm);
                float bs = p;
                for (int off = 16; off; off >>= 1)
                    bs += __shfl_xor_sync(0xffffffffu, bs, off);
                l = l * sc + bs;
                acc0 *= sc; acc1 *= sc;
                m = nm;
                const int cnt = (i - 256) / 128 + 1;
                for (int l2 = 0; l2 < cnt; l2++) {
                    const float pv = __shfl_sync(0xffffffffu, p, l2);
                    const int j2 = i - 256 - 128 * l2;
                    const float* vr = V + ((size_t)(b * S_ + j2)) * D_ + h * 64;
                    acc0 = fmaf(pv, __ldg(vr + lane), acc0);
                    acc1 = fmaf(pv, __ldg(vr + lane + 32), acc1);
                }
            }
        }

        // local window: 5 aligned 32-key segments
        const int u0 = o_in_blk >> 5;
#pragma unroll 1
        for (int t = 0; t < 5; t++) {
            const int koff = (u0 + t) * 32;
            const int j = base_row + koff + lane;
            float s = -INFINITY;
            if (j >= 0 && j >= i - 128 && j <= i) {
                const float4* kr = reinterpret_cast<const float4*>(Ks + (koff + lane) * KP);
                float dv = 0.f;
#pragma unroll
                for (int d = 0; d < 16; d++) {
                    const float4 kv = kr[d];
                    dv = fmaf(rq[d].x, kv.x, dv);
                    dv = fmaf(rq[d].y, kv.y, dv);
                    dv = fmaf(rq[d].z, kv.z, dv);
                    dv = fmaf(rq[d].w, kv.w, dv);
                }
                s = dv * 0.125f;
                if (mrow[j] == 0) s = NEG_;
            }
            float bm = s;
            for (int off = 16; off; off >>= 1)
                bm = fmaxf(bm, __shfl_xor_sync(0xffffffffu, bm, off));
            if (bm > -1e37f) {
                const float nm = fmaxf(m, bm);
                const float sc = __expf(m - nm);
                const float p = __expf(s - nm);
                float bs = p;
                for (int off = 16; off; off >>= 1)
                    bs += __shfl_xor_sync(0xffffffffu, bs, off);
                l = l * sc + bs;
                acc0 *= sc; acc1 *= sc;
                m = nm;

                __syncwarp();
                pb[lane] = p;
                __syncwarp();
                const float4* pv4 = reinterpret_cast<const float4*>(pb);
                const float4* v0 = reinterpret_cast<const float4*>(Vt + lane * VP + koff);
                const float4* v1 = reinterpret_cast<const float4*>(Vt + (lane + 32) * VP + koff);
#pragma unroll
                for (int kk = 0; kk < 8; kk++) {
                    const float4 pp = pv4[kk];
                    const float4 va = v0[kk];
                    const float4 vb = v1[kk];
                    acc0 = fmaf(pp.x, va.x, acc0);
                    acc0 = fmaf(pp.y, va.y, acc0);
                    acc0 = fmaf(pp.z, va.z, acc0);
                    acc0 = fmaf(pp.w, va.w, acc0);
                    acc1 = fmaf(pp.x, vb.x, acc1);
                    acc1 = fmaf(pp.y, vb.y, acc1);
                    acc1 = fmaf(pp.z, vb.z, acc1);
                    acc1 = fmaf(pp.w, vb.w, acc1);
                }
            }
        }

        const float inv = 1.0f / l;
        float* orow = O + ((size_t)(b * S_ + i)) * D_ + h * 64;
        orow[lane]      = __uint_as_float(f2tf32(acc0 * inv));
        orow[lane + 32] = __uint_as_float(f2tf32(acc1 * inv));
    }
}

// ---------------- host launcher ----------------
extern "C" void kernel_launch(void* const* d_in, const int* in_sizes, int n_in,
                              void* d_out, int out_size)
{
    (void)in_sizes; (void)n_in; (void)out_size;
    const float* x    = (const float*)d_in[0];
    const int*   mask = (const int*)  d_in[1];
    const float* Wq = (const float*)d_in[2];  const float* bq = (const float*)d_in[3];
    const float* Wk = (const float*)d_in[4];  const float* bk = (const float*)d_in[5];
    const float* Wv = (const float*)d_in[6];  const float* bv = (const float*)d_in[7];
    const float* Wo = (const float*)d_in[8];  const float* bo = (const float*)d_in[9];
    const float* W1 = (const float*)d_in[10]; const float* bf1 = (const float*)d_in[11];
    const float* W2 = (const float*)d_in[12]; const float* bf2 = (const float*)d_in[13];
    const float* g1 = (const float*)d_in[14]; const float* bl1 = (const float*)d_in[15];
    const float* g2 = (const float*)d_in[16]; const float* bl2 = (const float*)d_in[17];
    float* out = (float*)d_out;

    float *n1, *q, *k, *v, *o, *x1, *n2, *ff;
    uint32_t *Wqc, *Wkc, *Wvc, *Woc, *W1c, *W2c;
    cudaGetSymbolAddress((void**)&n1, g_n1);
    cudaGetSymbolAddress((void**)&q,  g_q);
    cudaGetSymbolAddress((void**)&k,  g_k);
    cudaGetSymbolAddress((void**)&v,  g_v);
    cudaGetSymbolAddress((void**)&o,  g_o);
    cudaGetSymbolAddress((void**)&x1, g_x1);
    cudaGetSymbolAddress((void**)&n2, g_n2);
    cudaGetSymbolAddress((void**)&ff, g_ff);
    cudaGetSymbolAddress((void**)&Wqc, g_Wqc);
    cudaGetSymbolAddress((void**)&Wkc, g_Wkc);
    cudaGetSymbolAddress((void**)&Wvc, g_Wvc);
    cudaGetSymbolAddress((void**)&Woc, g_Woc);
    cudaGetSymbolAddress((void**)&W1c, g_W1c);
    cudaGetSymbolAddress((void**)&W2c, g_W2c);

    cudaFuncSetAttribute(mmagemm_kernel, cudaFuncAttributeMaxDynamicSharedMemorySize, GEMM_SMEM);
    cudaFuncSetAttribute(attn3_kernel, cudaFuncAttributeMaxDynamicSharedMemorySize, ATTN_SMEM);

    const int M = B_ * S_;  // 4096

    // 0) weight pre-convert to tf32 bits
    cvtw_kernel<<<(D_ * D_) / 1024, 256>>>(Wq, Wqc);
    cvtw_kernel<<<(D_ * D_) / 1024, 256>>>(Wk, Wkc);
    cvtw_kernel<<<(D_ * D_) / 1024, 256>>>(Wv, Wvc);
    cvtw_kernel<<<(D_ * D_) / 1024, 256>>>(Wo, Woc);
    cvtw_kernel<<<(D_ * FF_) / 1024, 256>>>(W1, W1c);
    cvtw_kernel<<<(FF_ * D_) / 1024, 256>>>(W2, W2c);

    // 1) LN1 -> n1 (tf32)
    ln_kernel<<<M, 256>>>(x, g1, bl1, n1);

    // 2) Q, K, V projections
    {
        dim3 grid(D_ / BN, M / BM);
        mmagemm_kernel<<<grid, 256, GEMM_SMEM>>>((const uint32_t*)n1, Wqc, bq, nullptr, q, M, D_, D_, 0, 0);
        mmagemm_kernel<<<grid, 256, GEMM_SMEM>>>((const uint32_t*)n1, Wkc, bk, nullptr, k, M, D_, D_, 0, 0);
        mmagemm_kernel<<<grid, 256, GEMM_SMEM>>>((const uint32_t*)n1, Wvc, bv, nullptr, v, M, D_, D_, 0, 0);
    }

    // 3) sparse attention -> o (tf32)
    {
        dim3 grid(S_ / QB, H_, B_);
        attn3_kernel<<<grid, 256, ATTN_SMEM>>>(q, k, v, mask, o);
    }

    // 4) output projection + residual -> x1 (fp32)
    {
        dim3 grid(D_ / BN, M / BM);
        mmagemm_kernel<<<grid, 256, GEMM_SMEM>>>((const uint32_t*)o, Woc, bo, x, x1, M, D_, D_, 0, 0);
    }

    // 5) LN2 -> n2 (tf32)
    ln_kernel<<<M, 256>>>(x1, g2, bl2, n2);

    // 6) FFN up + GELU -> ff (tf32)
    {
        dim3 grid(FF_ / BN, M / BM);
        mmagemm_kernel<<<grid, 256, GEMM_SMEM>>>((const uint32_t*)n2, W1c, bf1, nullptr, ff, M, FF_, D_, 1, 1);
    }

    // 7) FFN down + residual -> out (fp32)
    {
        dim3 grid(D_ / BN, M / BM);
        mmagemm_kernel<<<grid, 256, GEMM_SMEM>>>((const uint32_t*)ff, W2c, bf2, x1, out, M, D_, FF_, 0, 0);
    }
}

// round 13
// speedup vs baseline: 1.1046x; 1.0697x over previous
#include <cuda_runtime.h>
#include <math.h>
#include <stdint.h>

#define B_ 2
#define S_ 2048
#define D_ 1024
#define H_ 16
#define DK_ 64
#define FF_ 4096
#define NEG_ (-1000000000.0f)

// ---------------- scratch buffers ----------------
__device__ float g_n1[(size_t)B_ * S_ * D_];    // tf32 bits
__device__ float g_q [(size_t)B_ * S_ * D_];    // fp32
__device__ float g_k [(size_t)B_ * S_ * D_];    // fp32
__device__ float g_v [(size_t)B_ * S_ * D_];    // fp32
__device__ float g_o [(size_t)B_ * S_ * D_];    // tf32 bits
__device__ float g_x1[(size_t)B_ * S_ * D_];    // fp32
__device__ float g_n2[(size_t)B_ * S_ * D_];    // tf32 bits
__device__ float g_ff[(size_t)B_ * S_ * FF_];   // tf32 bits

__device__ __forceinline__ uint32_t f2tf32(float f) {
    uint32_t r; asm("cvt.rna.tf32.f32 %0, %1;" : "=r"(r) : "f"(f)); return r;
}

__device__ __forceinline__ void mma_tf32(float c[4], const uint32_t a[4], const uint32_t b[2]) {
    asm volatile(
        "mma.sync.aligned.m16n8k8.row.col.f32.tf32.tf32.f32 "
        "{%0,%1,%2,%3}, {%4,%5,%6,%7}, {%8,%9}, {%0,%1,%2,%3};"
        : "+f"(c[0]), "+f"(c[1]), "+f"(c[2]), "+f"(c[3])
        : "r"(a[0]), "r"(a[1]), "r"(a[2]), "r"(a[3]), "r"(b[0]), "r"(b[1]));
}

// ================= tf32 tensor-core GEMM (R8 structure) =======================
// C[M,N] = act(A[M,K] @ W[K,N] + bias) (+res)
// A: tf32 bits [M,K] (producers emit tf32). W: raw fp32 [K,N], converted with
// cvt.rna in the B-staging path (R4-proven; conversion hidden under LDG latency).
#define BM 128
#define BN 128
#define BK 16

__global__ __launch_bounds__(256) void mmagemm_kernel(const uint32_t* __restrict__ A,
                                                      const float* __restrict__ W,
                                                      const float* __restrict__ bias,
                                                      const float* __restrict__ res,
                                                      float* __restrict__ C,
                                                      int M, int N, int K, int act, int outtf)
{
    __shared__ alignas(128) char Asm[2 * 8192];
    __shared__ alignas(128) char Bsm[2 * 8192];

    const int tid = threadIdx.x;
    const int wid = tid >> 5, lane = tid & 31;
    const int row0 = blockIdx.y * BM;
    const int col0 = blockIdx.x * BN;

    const int m0w = (wid >> 2) * 64;
    const int n0w = (wid & 3) * 32;
    const int g16b = m0w >> 4;
    const int bg8 = n0w >> 3;

    const int ar = tid >> 2;
    const int ac = (tid & 3) << 2;
    const int lga = ar & 7;
    const int swa = (lga >> 1) & 3;
    const int abase = ((ac >> 3) * 8 + (ar >> 4)) * 512 +
                      ((((ac >> 2) & 1) * 2) + ((ar >> 3) & 1)) * 4;
    int aoff[4];
#pragma unroll
    for (int j = 0; j < 4; j++) aoff[j] = abase + (((lga * 4 + j) ^ swa) << 4);

    const int kq = tid >> 6;
    const int nn = tid & 63;
    int boff[2][2];
#pragma unroll
    for (int t = 0; t < 2; t++) {
        const int nv = nn + t * 64;
        const int g8 = nv >> 3;
        const int slot = (((nv & 7) * 4 + kq) ^ (g8 & 3));
#pragma unroll
        for (int kb = 0; kb < 2; kb++)
            boff[t][kb] = ((kb * 16 + g8) << 8) + slot * 8;
    }

    const int aslot = ((lane ^ ((lane >> 3) & 3)) << 4);

    float acc[4][4][4];
#pragma unroll
    for (int mi = 0; mi < 4; mi++)
#pragma unroll
        for (int ni = 0; ni < 4; ni++)
#pragma unroll
            for (int r = 0; r < 4; r++) acc[mi][ni][r] = 0.f;

    const int NC = K / BK;

    // prologue: chunk 0 -> buffer 0
    {
        const uint4 av0 = *reinterpret_cast<const uint4*>(A + (size_t)(row0 + ar) * K + ac);
        const uint4 av1 = *reinterpret_cast<const uint4*>(A + (size_t)(row0 + 64 + ar) * K + ac);
        const uint32_t a0[4] = {av0.x, av0.y, av0.z, av0.w};
        const uint32_t a1[4] = {av1.x, av1.y, av1.z, av1.w};
#pragma unroll
        for (int j = 0; j < 4; j++) {
            *reinterpret_cast<uint32_t*>(Asm + aoff[j]) = a0[j];
            *reinterpret_cast<uint32_t*>(Asm + aoff[j] + 2048) = a1[j];
        }
        float wreg[2][4];
#pragma unroll
        for (int t = 0; t < 2; t++)
#pragma unroll
            for (int s = 0; s < 4; s++)
                wreg[t][s] = W[(size_t)(kq + s * 4) * N + col0 + nn + t * 64];
#pragma unroll
        for (int t = 0; t < 2; t++)
#pragma unroll
            for (int kb = 0; kb < 2; kb++) {
                uint2 u = {f2tf32(wreg[t][kb * 2 + 0]), f2tf32(wreg[t][kb * 2 + 1])};
                *reinterpret_cast<uint2*>(Bsm + boff[t][kb]) = u;
            }
    }
    __syncthreads();

    for (int c = 0; c < NC; c++) {
        const int buf = c & 1;
        const char* Ab = Asm + buf * 8192;
        const char* Bb = Bsm + buf * 8192;

        uint4 av0, av1;
        float wreg[2][4];
        if (c + 1 < NC) {
            const int k0 = (c + 1) * BK;
            av0 = *reinterpret_cast<const uint4*>(A + (size_t)(row0 + ar) * K + k0 + ac);
            av1 = *reinterpret_cast<const uint4*>(A + (size_t)(row0 + 64 + ar) * K + k0 + ac);
#pragma unroll
            for (int t = 0; t < 2; t++)
#pragma unroll
                for (int s = 0; s < 4; s++)
                    wreg[t][s] = W[(size_t)(k0 + kq + s * 4) * N + col0 + nn + t * 64];
        }

#pragma unroll
        for (int kb = 0; kb < 2; kb++) {
            const char* Abk = Ab + (kb << 12);
            const char* Bbk = Bb + (kb << 12);
            uint4 afr[4];
            uint2 bfr[4];
#pragma unroll
            for (int mi = 0; mi < 4; mi++)
                afr[mi] = *reinterpret_cast<const uint4*>(Abk + ((g16b + mi) << 9) + aslot);
#pragma unroll
            for (int ni = 0; ni < 4; ni++) {
                const int g8 = bg8 + ni;
                bfr[ni] = *reinterpret_cast<const uint2*>(Bbk + (g8 << 8) + ((lane ^ (g8 & 3)) << 3));
            }
#pragma unroll
            for (int mi = 0; mi < 4; mi++)
#pragma unroll
                for (int ni = 0; ni < 4; ni++)
                    mma_tf32(acc[mi][ni],
                             reinterpret_cast<const uint32_t*>(&afr[mi]),
                             reinterpret_cast<const uint32_t*>(&bfr[ni]));
        }

        if (c + 1 < NC) {
            // single-sync double buffer (R8-proven)
            char* An = Asm + (buf ^ 1) * 8192;
            char* Bn = Bsm + (buf ^ 1) * 8192;
            const uint32_t a0[4] = {av0.x, av0.y, av0.z, av0.w};
            const uint32_t a1[4] = {av1.x, av1.y, av1.z, av1.w};
#pragma unroll
            for (int j = 0; j < 4; j++) {
                *reinterpret_cast<uint32_t*>(An + aoff[j]) = a0[j];
                *reinterpret_cast<uint32_t*>(An + aoff[j] + 2048) = a1[j];
            }
#pragma unroll
            for (int t = 0; t < 2; t++)
#pragma unroll
                for (int kb = 0; kb < 2; kb++) {
                    uint2 u = {f2tf32(wreg[t][kb * 2 + 0]), f2tf32(wreg[t][kb * 2 + 1])};
                    *reinterpret_cast<uint2*>(Bn + boff[t][kb]) = u;
                }
            __syncthreads();
        }
    }

    // epilogue
    const int lg = lane >> 2, lt = lane & 3;
#pragma unroll
    for (int mi = 0; mi < 4; mi++) {
#pragma unroll
        for (int half = 0; half < 2; half++) {
            const int r = row0 + m0w + mi * 16 + lg + half * 8;
#pragma unroll
            for (int ni = 0; ni < 4; ni++) {
                const int cc = col0 + n0w + ni * 8 + lt * 2;
                float2 o;
                o.x = acc[mi][ni][half * 2 + 0] + bias[cc];
                o.y = acc[mi][ni][half * 2 + 1] + bias[cc + 1];
                if (act == 1) {
                    o.x = 0.5f * o.x * (1.0f + erff(o.x * 0.70710678118654752f));
                    o.y = 0.5f * o.y * (1.0f + erff(o.y * 0.70710678118654752f));
                }
                if (res) {
                    const float2 rv = *reinterpret_cast<const float2*>(res + (size_t)r * N + cc);
                    o.x += rv.x; o.y += rv.y;
                }
                if (outtf) {
                    o.x = __uint_as_float(f2tf32(o.x));
                    o.y = __uint_as_float(f2tf32(o.y));
                }
                *reinterpret_cast<float2*>(C + (size_t)r * N + cc) = o;
            }
        }
    }
}

// ---------------- LayerNorm (emits tf32 bits) ----------------
__global__ __launch_bounds__(256) void ln_kernel(const float* __restrict__ x,
                                                 const float* __restrict__ g,
                                                 const float* __restrict__ b,
                                                 float* __restrict__ out)
{
    const int row = blockIdx.x;
    const float* xr = x + (size_t)row * D_;
    float* outr = out + (size_t)row * D_;
    const int tid = threadIdx.x;

    float4 v = reinterpret_cast<const float4*>(xr)[tid];
    float s = v.x + v.y + v.z + v.w;
    float ss = v.x * v.x + v.y * v.y + v.z * v.z + v.w * v.w;

    __shared__ float sh_s[8], sh_ss[8];
    for (int off = 16; off; off >>= 1) {
        s  += __shfl_xor_sync(0xffffffffu, s, off);
        ss += __shfl_xor_sync(0xffffffffu, ss, off);
    }
    const int wid = tid >> 5, lane = tid & 31;
    if (lane == 0) { sh_s[wid] = s; sh_ss[wid] = ss; }
    __syncthreads();
    if (wid == 0) {
        s  = (lane < 8) ? sh_s[lane]  : 0.f;
        ss = (lane < 8) ? sh_ss[lane] : 0.f;
        for (int off = 4; off; off >>= 1) {
            s  += __shfl_xor_sync(0xffffffffu, s, off);
            ss += __shfl_xor_sync(0xffffffffu, ss, off);
        }
        if (lane == 0) { sh_s[0] = s; sh_ss[0] = ss; }
    }
    __syncthreads();
    const float mu = sh_s[0] * (1.0f / D_);
    const float var = sh_ss[0] * (1.0f / D_) - mu * mu;
    const float rstd = rsqrtf(var + 1e-5f);

    float4 gv = reinterpret_cast<const float4*>(g)[tid];
    float4 bv = reinterpret_cast<const float4*>(b)[tid];
    uint4 o;
    o.x = f2tf32((v.x - mu) * rstd * gv.x + bv.x);
    o.y = f2tf32((v.y - mu) * rstd * gv.y + bv.y);
    o.z = f2tf32((v.z - mu) * rstd * gv.z + bv.z);
    o.w = f2tf32((v.w - mu) * rstd * gv.w + bv.w);
    reinterpret_cast<uint4*>(outr)[tid] = o;
}

// ================= sparse attention v3 (R8 version) =================
#define QB 64
#define KW 192
#define KP 68
#define VP 196
#define ATTN_SMEM ((KW * KP + 64 * VP + 8 * 32) * 4)

__global__ __launch_bounds__(256) void attn3_kernel(const float* __restrict__ Q,
                                                    const float* __restrict__ K,
                                                    const float* __restrict__ V,
                                                    const int* __restrict__ mask,
                                                    float* __restrict__ O)
{
    extern __shared__ float smattn[];
    float* Ks  = smattn;
    float* Vt  = smattn + KW * KP;
    float* psm = smattn + KW * KP + 64 * VP;

    const int qb0 = blockIdx.x * QB;
    const int h = blockIdx.y;
    const int b = blockIdx.z;
    const int tid = threadIdx.x;
    const int warp = tid >> 5, lane = tid & 31;
    const int base_row = qb0 - 128;

    for (int idx = tid; idx < KW * 64; idx += 256) {
        const int r = idx >> 6, d = idx & 63;
        const int j = base_row + r;
        float kv = 0.f, vv = 0.f;
        if (j >= 0) {
            const size_t g = ((size_t)(b * S_ + j)) * D_ + h * 64 + d;
            kv = K[g]; vv = V[g];
        }
        Ks[r * KP + d] = kv;
        Vt[d * VP + r] = vv;
    }
    __syncthreads();

    float* pb = psm + warp * 32;

#pragma unroll 1
    for (int qi = 0; qi < 8; qi++) {
        const int i = qb0 + warp * 8 + qi;
        const int o_in_blk = warp * 8 + qi;
        const float4* q4 = reinterpret_cast<const float4*>(Q + ((size_t)(b * S_ + i)) * D_ + h * 64);
        float4 rq[16];
#pragma unroll
        for (int d = 0; d < 16; d++) rq[d] = __ldg(q4 + d);
        const int* mrow = mask + (size_t)i * S_;

        float m = -INFINITY, l = 0.f, acc0 = 0.f, acc1 = 0.f;

        // strided keys
        {
            const int j = i - 256 - 128 * lane;
            float s = -INFINITY;
            if (j >= 0) {
                const float4* kr = reinterpret_cast<const float4*>(K + ((size_t)(b * S_ + j)) * D_ + h * 64);
                float dv = 0.f;
#pragma unroll
                for (int d = 0; d < 16; d++) {
                    const float4 kv = __ldg(kr + d);
                    dv = fmaf(rq[d].x, kv.x, dv);
                    dv = fmaf(rq[d].y, kv.y, dv);
                    dv = fmaf(rq[d].z, kv.z, dv);
                    dv = fmaf(rq[d].w, kv.w, dv);
                }
                s = dv * 0.125f;
                if (mrow[j] == 0) s = NEG_;
            }
            float bm = s;
            for (int off = 16; off; off >>= 1)
                bm = fmaxf(bm, __shfl_xor_sync(0xffffffffu, bm, off));
            if (bm > -1e37f) {
                const float nm = fmaxf(m, bm);
                const float sc = __expf(m - nm);
                const float p = __expf(s - nm);
                float bs = p;
                for (int off = 16; off; off >>= 1)
                    bs += __shfl_xor_sync(0xffffffffu, bs, off);
                l = l * sc + bs;
                acc0 *= sc; acc1 *= sc;
                m = nm;
                const int cnt = (i - 256) / 128 + 1;
                for (int l2 = 0; l2 < cnt; l2++) {
                    const float pv = __shfl_sync(0xffffffffu, p, l2);
                    const int j2 = i - 256 - 128 * l2;
                    const float* vr = V + ((size_t)(b * S_ + j2)) * D_ + h * 64;
                    acc0 = fmaf(pv, __ldg(vr + lane), acc0);
                    acc1 = fmaf(pv, __ldg(vr + lane + 32), acc1);
                }
            }
        }

        // local window: 5 aligned 32-key segments
        const int u0 = o_in_blk >> 5;
#pragma unroll 1
        for (int t = 0; t < 5; t++) {
            const int koff = (u0 + t) * 32;
            const int j = base_row + koff + lane;
            float s = -INFINITY;
            if (j >= 0 && j >= i - 128 && j <= i) {
                const float4* kr = reinterpret_cast<const float4*>(Ks + (koff + lane) * KP);
                float dv = 0.f;
#pragma unroll
                for (int d = 0; d < 16; d++) {
                    const float4 kv = kr[d];
                    dv = fmaf(rq[d].x, kv.x, dv);
                    dv = fmaf(rq[d].y, kv.y, dv);
                    dv = fmaf(rq[d].z, kv.z, dv);
                    dv = fmaf(rq[d].w, kv.w, dv);
                }
                s = dv * 0.125f;
                if (mrow[j] == 0) s = NEG_;
            }
            float bm = s;
            for (int off = 16; off; off >>= 1)
                bm = fmaxf(bm, __shfl_xor_sync(0xffffffffu, bm, off));
            if (bm > -1e37f) {
                const float nm = fmaxf(m, bm);
                const float sc = __expf(m - nm);
                const float p = __expf(s - nm);
                float bs = p;
                for (int off = 16; off; off >>= 1)
                    bs += __shfl_xor_sync(0xffffffffu, bs, off);
                l = l * sc + bs;
                acc0 *= sc; acc1 *= sc;
                m = nm;

                __syncwarp();
                pb[lane] = p;
                __syncwarp();
                const float4* pv4 = reinterpret_cast<const float4*>(pb);
                const float4* v0 = reinterpret_cast<const float4*>(Vt + lane * VP + koff);
                const float4* v1 = reinterpret_cast<const float4*>(Vt + (lane + 32) * VP + koff);
#pragma unroll
                for (int kk = 0; kk < 8; kk++) {
                    const float4 pp = pv4[kk];
                    const float4 va = v0[kk];
                    const float4 vb = v1[kk];
                    acc0 = fmaf(pp.x, va.x, acc0);
                    acc0 = fmaf(pp.y, va.y, acc0);
                    acc0 = fmaf(pp.z, va.z, acc0);
                    acc0 = fmaf(pp.w, va.w, acc0);
                    acc1 = fmaf(pp.x, vb.x, acc1);
                    acc1 = fmaf(pp.y, vb.y, acc1);
                    acc1 = fmaf(pp.z, vb.z, acc1);
                    acc1 = fmaf(pp.w, vb.w, acc1);
                }
            }
        }

        const float inv = 1.0f / l;
        float* orow = O + ((size_t)(b * S_ + i)) * D_ + h * 64;
        orow[lane]      = __uint_as_float(f2tf32(acc0 * inv));
        orow[lane + 32] = __uint_as_float(f2tf32(acc1 * inv));
    }
}

// ---------------- host launcher ----------------
extern "C" void kernel_launch(void* const* d_in, const int* in_sizes, int n_in,
                              void* d_out, int out_size)
{
    (void)in_sizes; (void)n_in; (void)out_size;
    const float* x    = (const float*)d_in[0];
    const int*   mask = (const int*)  d_in[1];
    const float* Wq = (const float*)d_in[2];  const float* bq = (const float*)d_in[3];
    const float* Wk = (const float*)d_in[4];  const float* bk = (const float*)d_in[5];
    const float* Wv = (const float*)d_in[6];  const float* bv = (const float*)d_in[7];
    const float* Wo = (const float*)d_in[8];  const float* bo = (const float*)d_in[9];
    const float* W1 = (const float*)d_in[10]; const float* bf1 = (const float*)d_in[11];
    const float* W2 = (const float*)d_in[12]; const float* bf2 = (const float*)d_in[13];
    const float* g1 = (const float*)d_in[14]; const float* bl1 = (const float*)d_in[15];
    const float* g2 = (const float*)d_in[16]; const float* bl2 = (const float*)d_in[17];
    float* out = (float*)d_out;

    float *n1, *q, *k, *v, *o, *x1, *n2, *ff;
    cudaGetSymbolAddress((void**)&n1, g_n1);
    cudaGetSymbolAddress((void**)&q,  g_q);
    cudaGetSymbolAddress((void**)&k,  g_k);
    cudaGetSymbolAddress((void**)&v,  g_v);
    cudaGetSymbolAddress((void**)&o,  g_o);
    cudaGetSymbolAddress((void**)&x1, g_x1);
    cudaGetSymbolAddress((void**)&n2, g_n2);
    cudaGetSymbolAddress((void**)&ff, g_ff);

    cudaFuncSetAttribute(attn3_kernel, cudaFuncAttributeMaxDynamicSharedMemorySize, ATTN_SMEM);

    const int M = B_ * S_;  // 4096

    // 1) LN1 -> n1 (tf32)
    ln_kernel<<<M, 256>>>(x, g1, bl1, n1);

    // 2) Q, K, V projections (weights consumed directly, cvt in-loop)
    {
        dim3 grid(D_ / BN, M / BM);
        mmagemm_kernel<<<grid, 256>>>((const uint32_t*)n1, Wq, bq, nullptr, q, M, D_, D_, 0, 0);
        mmagemm_kernel<<<grid, 256>>>((const uint32_t*)n1, Wk, bk, nullptr, k, M, D_, D_, 0, 0);
        mmagemm_kernel<<<grid, 256>>>((const uint32_t*)n1, Wv, bv, nullptr, v, M, D_, D_, 0, 0);
    }

    // 3) sparse attention -> o (tf32)
    {
        dim3 grid(S_ / QB, H_, B_);
        attn3_kernel<<<grid, 256, ATTN_SMEM>>>(q, k, v, mask, o);
    }

    // 4) output projection + residual -> x1 (fp32)
    {
        dim3 grid(D_ / BN, M / BM);
        mmagemm_kernel<<<grid, 256>>>((const uint32_t*)o, Wo, bo, x, x1, M, D_, D_, 0, 0);
    }

    // 5) LN2 -> n2 (tf32)
    ln_kernel<<<M, 256>>>(x1, g2, bl2, n2);

    // 6) FFN up + GELU -> ff (tf32)
    {
        dim3 grid(FF_ / BN, M / BM);
        mmagemm_kernel<<<grid, 256>>>((const uint32_t*)n2, W1, bf1, nullptr, ff, M, FF_, D_, 1, 1);
    }

    // 7) FFN down + residual -> out (fp32)
    {
        dim3 grid(D_ / BN, M / BM);
        mmagemm_kernel<<<grid, 256>>>((const uint32_t*)ff, W2, bf2, x1, out, M, D_, FF_, 0, 0);
    }
}

// round 14
// speedup vs baseline: 1.1258x; 1.0192x over previous
#include <cuda_runtime.h>
#include <math.h>
#include <stdint.h>

#define B_ 2
#define S_ 2048
#define D_ 1024
#define H_ 16
#define DK_ 64
#define FF_ 4096
#define NEG_ (-1000000000.0f)

// ---------------- scratch buffers ----------------
__device__ float g_n1[(size_t)B_ * S_ * D_];    // tf32 bits
__device__ float g_q [(size_t)B_ * S_ * D_];    // fp32
__device__ float g_k [(size_t)B_ * S_ * D_];    // fp32
__device__ float g_v [(size_t)B_ * S_ * D_];    // fp32
__device__ float g_o [(size_t)B_ * S_ * D_];    // tf32 bits
__device__ float g_x1[(size_t)B_ * S_ * D_];    // fp32
__device__ float g_n2[(size_t)B_ * S_ * D_];    // tf32 bits
__device__ float g_ff[(size_t)B_ * S_ * FF_];   // tf32 bits

__device__ __forceinline__ uint32_t f2tf32(float f) {
    uint32_t r; asm("cvt.rna.tf32.f32 %0, %1;" : "=r"(r) : "f"(f)); return r;
}

__device__ __forceinline__ void mma_tf32(float c[4], const uint32_t a[4], const uint32_t b[2]) {
    asm volatile(
        "mma.sync.aligned.m16n8k8.row.col.f32.tf32.tf32.f32 "
        "{%0,%1,%2,%3}, {%4,%5,%6,%7}, {%8,%9}, {%0,%1,%2,%3};"
        : "+f"(c[0]), "+f"(c[1]), "+f"(c[2]), "+f"(c[3])
        : "r"(a[0]), "r"(a[1]), "r"(a[2]), "r"(a[3]), "r"(b[0]), "r"(b[1]));
}

// ================= tf32 tensor-core GEMM (R13 champion, unchanged) ============
#define BM 128
#define BN 128
#define BK 16

__global__ __launch_bounds__(256) void mmagemm_kernel(const uint32_t* __restrict__ A,
                                                      const float* __restrict__ W,
                                                      const float* __restrict__ bias,
                                                      const float* __restrict__ res,
                                                      float* __restrict__ C,
                                                      int M, int N, int K, int act, int outtf)
{
    __shared__ alignas(128) char Asm[2 * 8192];
    __shared__ alignas(128) char Bsm[2 * 8192];

    const int tid = threadIdx.x;
    const int wid = tid >> 5, lane = tid & 31;
    const int row0 = blockIdx.y * BM;
    const int col0 = blockIdx.x * BN;

    const int m0w = (wid >> 2) * 64;
    const int n0w = (wid & 3) * 32;
    const int g16b = m0w >> 4;
    const int bg8 = n0w >> 3;

    const int ar = tid >> 2;
    const int ac = (tid & 3) << 2;
    const int lga = ar & 7;
    const int swa = (lga >> 1) & 3;
    const int abase = ((ac >> 3) * 8 + (ar >> 4)) * 512 +
                      ((((ac >> 2) & 1) * 2) + ((ar >> 3) & 1)) * 4;
    int aoff[4];
#pragma unroll
    for (int j = 0; j < 4; j++) aoff[j] = abase + (((lga * 4 + j) ^ swa) << 4);

    const int kq = tid >> 6;
    const int nn = tid & 63;
    int boff[2][2];
#pragma unroll
    for (int t = 0; t < 2; t++) {
        const int nv = nn + t * 64;
        const int g8 = nv >> 3;
        const int slot = (((nv & 7) * 4 + kq) ^ (g8 & 3));
#pragma unroll
        for (int kb = 0; kb < 2; kb++)
            boff[t][kb] = ((kb * 16 + g8) << 8) + slot * 8;
    }

    const int aslot = ((lane ^ ((lane >> 3) & 3)) << 4);

    float acc[4][4][4];
#pragma unroll
    for (int mi = 0; mi < 4; mi++)
#pragma unroll
        for (int ni = 0; ni < 4; ni++)
#pragma unroll
            for (int r = 0; r < 4; r++) acc[mi][ni][r] = 0.f;

    const int NC = K / BK;

    // prologue: chunk 0 -> buffer 0
    {
        const uint4 av0 = *reinterpret_cast<const uint4*>(A + (size_t)(row0 + ar) * K + ac);
        const uint4 av1 = *reinterpret_cast<const uint4*>(A + (size_t)(row0 + 64 + ar) * K + ac);
        const uint32_t a0[4] = {av0.x, av0.y, av0.z, av0.w};
        const uint32_t a1[4] = {av1.x, av1.y, av1.z, av1.w};
#pragma unroll
        for (int j = 0; j < 4; j++) {
            *reinterpret_cast<uint32_t*>(Asm + aoff[j]) = a0[j];
            *reinterpret_cast<uint32_t*>(Asm + aoff[j] + 2048) = a1[j];
        }
        float wreg[2][4];
#pragma unroll
        for (int t = 0; t < 2; t++)
#pragma unroll
            for (int s = 0; s < 4; s++)
                wreg[t][s] = W[(size_t)(kq + s * 4) * N + col0 + nn + t * 64];
#pragma unroll
        for (int t = 0; t < 2; t++)
#pragma unroll
            for (int kb = 0; kb < 2; kb++) {
                uint2 u = {f2tf32(wreg[t][kb * 2 + 0]), f2tf32(wreg[t][kb * 2 + 1])};
                *reinterpret_cast<uint2*>(Bsm + boff[t][kb]) = u;
            }
    }
    __syncthreads();

    for (int c = 0; c < NC; c++) {
        const int buf = c & 1;
        const char* Ab = Asm + buf * 8192;
        const char* Bb = Bsm + buf * 8192;

        uint4 av0, av1;
        float wreg[2][4];
        if (c + 1 < NC) {
            const int k0 = (c + 1) * BK;
            av0 = *reinterpret_cast<const uint4*>(A + (size_t)(row0 + ar) * K + k0 + ac);
            av1 = *reinterpret_cast<const uint4*>(A + (size_t)(row0 + 64 + ar) * K + k0 + ac);
#pragma unroll
            for (int t = 0; t < 2; t++)
#pragma unroll
                for (int s = 0; s < 4; s++)
                    wreg[t][s] = W[(size_t)(k0 + kq + s * 4) * N + col0 + nn + t * 64];
        }

#pragma unroll
        for (int kb = 0; kb < 2; kb++) {
            const char* Abk = Ab + (kb << 12);
            const char* Bbk = Bb + (kb << 12);
            uint4 afr[4];
            uint2 bfr[4];
#pragma unroll
            for (int mi = 0; mi < 4; mi++)
                afr[mi] = *reinterpret_cast<const uint4*>(Abk + ((g16b + mi) << 9) + aslot);
#pragma unroll
            for (int ni = 0; ni < 4; ni++) {
                const int g8 = bg8 + ni;
                bfr[ni] = *reinterpret_cast<const uint2*>(Bbk + (g8 << 8) + ((lane ^ (g8 & 3)) << 3));
            }
#pragma unroll
            for (int mi = 0; mi < 4; mi++)
#pragma unroll
                for (int ni = 0; ni < 4; ni++)
                    mma_tf32(acc[mi][ni],
                             reinterpret_cast<const uint32_t*>(&afr[mi]),
                             reinterpret_cast<const uint32_t*>(&bfr[ni]));
        }

        if (c + 1 < NC) {
            char* An = Asm + (buf ^ 1) * 8192;
            char* Bn = Bsm + (buf ^ 1) * 8192;
            const uint32_t a0[4] = {av0.x, av0.y, av0.z, av0.w};
            const uint32_t a1[4] = {av1.x, av1.y, av1.z, av1.w};
#pragma unroll
            for (int j = 0; j < 4; j++) {
                *reinterpret_cast<uint32_t*>(An + aoff[j]) = a0[j];
                *reinterpret_cast<uint32_t*>(An + aoff[j] + 2048) = a1[j];
            }
#pragma unroll
            for (int t = 0; t < 2; t++)
#pragma unroll
                for (int kb = 0; kb < 2; kb++) {
                    uint2 u = {f2tf32(wreg[t][kb * 2 + 0]), f2tf32(wreg[t][kb * 2 + 1])};
                    *reinterpret_cast<uint2*>(Bn + boff[t][kb]) = u;
                }
            __syncthreads();
        }
    }

    // epilogue
    const int lg = lane >> 2, lt = lane & 3;
#pragma unroll
    for (int mi = 0; mi < 4; mi++) {
#pragma unroll
        for (int half = 0; half < 2; half++) {
            const int r = row0 + m0w + mi * 16 + lg + half * 8;
#pragma unroll
            for (int ni = 0; ni < 4; ni++) {
                const int cc = col0 + n0w + ni * 8 + lt * 2;
                float2 o;
                o.x = acc[mi][ni][half * 2 + 0] + bias[cc];
                o.y = acc[mi][ni][half * 2 + 1] + bias[cc + 1];
                if (act == 1) {
                    o.x = 0.5f * o.x * (1.0f + erff(o.x * 0.70710678118654752f));
                    o.y = 0.5f * o.y * (1.0f + erff(o.y * 0.70710678118654752f));
                }
                if (res) {
                    const float2 rv = *reinterpret_cast<const float2*>(res + (size_t)r * N + cc);
                    o.x += rv.x; o.y += rv.y;
                }
                if (outtf) {
                    o.x = __uint_as_float(f2tf32(o.x));
                    o.y = __uint_as_float(f2tf32(o.y));
                }
                *reinterpret_cast<float2*>(C + (size_t)r * N + cc) = o;
            }
        }
    }
}

// ---------------- LayerNorm (emits tf32 bits) ----------------
__global__ __launch_bounds__(256) void ln_kernel(const float* __restrict__ x,
                                                 const float* __restrict__ g,
                                                 const float* __restrict__ b,
                                                 float* __restrict__ out)
{
    const int row = blockIdx.x;
    const float* xr = x + (size_t)row * D_;
    float* outr = out + (size_t)row * D_;
    const int tid = threadIdx.x;

    float4 v = reinterpret_cast<const float4*>(xr)[tid];
    float s = v.x + v.y + v.z + v.w;
    float ss = v.x * v.x + v.y * v.y + v.z * v.z + v.w * v.w;

    __shared__ float sh_s[8], sh_ss[8];
    for (int off = 16; off; off >>= 1) {
        s  += __shfl_xor_sync(0xffffffffu, s, off);
        ss += __shfl_xor_sync(0xffffffffu, ss, off);
    }
    const int wid = tid >> 5, lane = tid & 31;
    if (lane == 0) { sh_s[wid] = s; sh_ss[wid] = ss; }
    __syncthreads();
    if (wid == 0) {
        s  = (lane < 8) ? sh_s[lane]  : 0.f;
        ss = (lane < 8) ? sh_ss[lane] : 0.f;
        for (int off = 4; off; off >>= 1) {
            s  += __shfl_xor_sync(0xffffffffu, s, off);
            ss += __shfl_xor_sync(0xffffffffu, ss, off);
        }
        if (lane == 0) { sh_s[0] = s; sh_ss[0] = ss; }
    }
    __syncthreads();
    const float mu = sh_s[0] * (1.0f / D_);
    const float var = sh_ss[0] * (1.0f / D_) - mu * mu;
    const float rstd = rsqrtf(var + 1e-5f);

    float4 gv = reinterpret_cast<const float4*>(g)[tid];
    float4 bv = reinterpret_cast<const float4*>(b)[tid];
    uint4 o;
    o.x = f2tf32((v.x - mu) * rstd * gv.x + bv.x);
    o.y = f2tf32((v.y - mu) * rstd * gv.y + bv.y);
    o.z = f2tf32((v.z - mu) * rstd * gv.z + bv.z);
    o.w = f2tf32((v.w - mu) * rstd * gv.w + bv.w);
    reinterpret_cast<uint4*>(outr)[tid] = o;
}

// ================= sparse attention v4: two-pass exact softmax ================
// Pass 1: all 6 score groups (1 strided lane-set + 5 local segments) computed
// independently (memory latency overlaps). One max-reduce + one sum-reduce.
// Pass 2: unscaled P.V accumulation.
#define QB 64
#define KW 192
#define KP 68
#define VP 196
#define ATTN_SMEM ((KW * KP + 64 * VP + 8 * 32) * 4)

__global__ __launch_bounds__(256) void attn4_kernel(const float* __restrict__ Q,
                                                    const float* __restrict__ K,
                                                    const float* __restrict__ V,
                                                    const int* __restrict__ mask,
                                                    float* __restrict__ O)
{
    extern __shared__ float smattn[];
    float* Ks  = smattn;
    float* Vt  = smattn + KW * KP;
    float* psm = smattn + KW * KP + 64 * VP;

    const int qb0 = blockIdx.x * QB;
    const int h = blockIdx.y;
    const int b = blockIdx.z;
    const int tid = threadIdx.x;
    const int warp = tid >> 5, lane = tid & 31;
    const int base_row = qb0 - 128;

    for (int idx = tid; idx < KW * 64; idx += 256) {
        const int r = idx >> 6, d = idx & 63;
        const int j = base_row + r;
        float kv = 0.f, vv = 0.f;
        if (j >= 0) {
            const size_t g = ((size_t)(b * S_ + j)) * D_ + h * 64 + d;
            kv = K[g]; vv = V[g];
        }
        Ks[r * KP + d] = kv;
        Vt[d * VP + r] = vv;
    }
    __syncthreads();

    float* pb = psm + warp * 32;

#pragma unroll 1
    for (int qi = 0; qi < 8; qi++) {
        const int i = qb0 + warp * 8 + qi;
        const int o_in_blk = warp * 8 + qi;
        const float4* q4 = reinterpret_cast<const float4*>(Q + ((size_t)(b * S_ + i)) * D_ + h * 64);
        float4 rq[16];
#pragma unroll
        for (int d = 0; d < 16; d++) rq[d] = __ldg(q4 + d);
        const int* mrow = mask + (size_t)i * S_;
        const int u0 = o_in_blk >> 5;

        // ---- pass 1a: strided score (lane l -> key j = i-256-128l) ----
        float s_str = -INFINITY;
        {
            const int j = i - 256 - 128 * lane;
            if (j >= 0) {
                const float4* kr = reinterpret_cast<const float4*>(K + ((size_t)(b * S_ + j)) * D_ + h * 64);
                float dv = 0.f;
#pragma unroll
                for (int d = 0; d < 16; d++) {
                    const float4 kv = __ldg(kr + d);
                    dv = fmaf(rq[d].x, kv.x, dv);
                    dv = fmaf(rq[d].y, kv.y, dv);
                    dv = fmaf(rq[d].z, kv.z, dv);
                    dv = fmaf(rq[d].w, kv.w, dv);
                }
                s_str = dv * 0.125f;
                if (mrow[j] == 0) s_str = NEG_;
            }
        }

        // ---- pass 1b: local segment scores (independent) ----
        float s_loc[5];
#pragma unroll
        for (int t = 0; t < 5; t++) {
            const int koff = (u0 + t) * 32;
            const int j = base_row + koff + lane;
            float s = -INFINITY;
            if (j >= 0 && j >= i - 128 && j <= i) {
                const float4* kr = reinterpret_cast<const float4*>(Ks + (koff + lane) * KP);
                float dv = 0.f;
#pragma unroll
                for (int d = 0; d < 16; d++) {
                    const float4 kv = kr[d];
                    dv = fmaf(rq[d].x, kv.x, dv);
                    dv = fmaf(rq[d].y, kv.y, dv);
                    dv = fmaf(rq[d].z, kv.z, dv);
                    dv = fmaf(rq[d].w, kv.w, dv);
                }
                s = dv * 0.125f;
                if (mrow[j] == 0) s = NEG_;
            }
            s_loc[t] = s;
        }

        // ---- single max reduce (m always finite: key j=i is in-range) ----
        float m = s_str;
#pragma unroll
        for (int t = 0; t < 5; t++) m = fmaxf(m, s_loc[t]);
        for (int off = 16; off; off >>= 1)
            m = fmaxf(m, __shfl_xor_sync(0xffffffffu, m, off));

        // ---- probs + single sum reduce ----
        const float p_str = __expf(s_str - m);   // 0 for invalid lanes
        float p_loc[5];
        float l = p_str;
#pragma unroll
        for (int t = 0; t < 5; t++) { p_loc[t] = __expf(s_loc[t] - m); l += p_loc[t]; }
        for (int off = 16; off; off >>= 1)
            l += __shfl_xor_sync(0xffffffffu, l, off);

        // ---- pass 2: P.V (unscaled) ----
        float acc0 = 0.f, acc1 = 0.f;
#pragma unroll 1
        for (int t = 0; t < 5; t++) {
            const int koff = (u0 + t) * 32;
            __syncwarp();
            pb[lane] = p_loc[t];
            __syncwarp();
            const float4* pv4 = reinterpret_cast<const float4*>(pb);
            const float4* v0 = reinterpret_cast<const float4*>(Vt + lane * VP + koff);
            const float4* v1 = reinterpret_cast<const float4*>(Vt + (lane + 32) * VP + koff);
#pragma unroll
            for (int kk = 0; kk < 8; kk++) {
                const float4 pp = pv4[kk];
                const float4 va = v0[kk];
                const float4 vb = v1[kk];
                acc0 = fmaf(pp.x, va.x, acc0);
                acc0 = fmaf(pp.y, va.y, acc0);
                acc0 = fmaf(pp.z, va.z, acc0);
                acc0 = fmaf(pp.w, va.w, acc0);
                acc1 = fmaf(pp.x, vb.x, acc1);
                acc1 = fmaf(pp.y, vb.y, acc1);
                acc1 = fmaf(pp.z, vb.z, acc1);
                acc1 = fmaf(pp.w, vb.w, acc1);
            }
        }
        // strided P.V
        const int cnt = (i >= 256) ? (((i - 256) >> 7) + 1) : 0;
        for (int l2 = 0; l2 < cnt; l2++) {
            const float pv = __shfl_sync(0xffffffffu, p_str, l2);
            const int j2 = i - 256 - 128 * l2;
            const float* vr = V + ((size_t)(b * S_ + j2)) * D_ + h * 64;
            acc0 = fmaf(pv, __ldg(vr + lane), acc0);
            acc1 = fmaf(pv, __ldg(vr + lane + 32), acc1);
        }

        const float inv = 1.0f / l;
        float* orow = O + ((size_t)(b * S_ + i)) * D_ + h * 64;
        orow[lane]      = __uint_as_float(f2tf32(acc0 * inv));
        orow[lane + 32] = __uint_as_float(f2tf32(acc1 * inv));
    }
}

// ---------------- host launcher ----------------
extern "C" void kernel_launch(void* const* d_in, const int* in_sizes, int n_in,
                              void* d_out, int out_size)
{
    (void)in_sizes; (void)n_in; (void)out_size;
    const float* x    = (const float*)d_in[0];
    const int*   mask = (const int*)  d_in[1];
    const float* Wq = (const float*)d_in[2];  const float* bq = (const float*)d_in[3];
    const float* Wk = (const float*)d_in[4];  const float* bk = (const float*)d_in[5];
    const float* Wv = (const float*)d_in[6];  const float* bv = (const float*)d_in[7];
    const float* Wo = (const float*)d_in[8];  const float* bo = (const float*)d_in[9];
    const float* W1 = (const float*)d_in[10]; const float* bf1 = (const float*)d_in[11];
    const float* W2 = (const float*)d_in[12]; const float* bf2 = (const float*)d_in[13];
    const float* g1 = (const float*)d_in[14]; const float* bl1 = (const float*)d_in[15];
    const float* g2 = (const float*)d_in[16]; const float* bl2 = (const float*)d_in[17];
    float* out = (float*)d_out;

    float *n1, *q, *k, *v, *o, *x1, *n2, *ff;
    cudaGetSymbolAddress((void**)&n1, g_n1);
    cudaGetSymbolAddress((void**)&q,  g_q);
    cudaGetSymbolAddress((void**)&k,  g_k);
    cudaGetSymbolAddress((void**)&v,  g_v);
    cudaGetSymbolAddress((void**)&o,  g_o);
    cudaGetSymbolAddress((void**)&x1, g_x1);
    cudaGetSymbolAddress((void**)&n2, g_n2);
    cudaGetSymbolAddress((void**)&ff, g_ff);

    cudaFuncSetAttribute(attn4_kernel, cudaFuncAttributeMaxDynamicSharedMemorySize, ATTN_SMEM);

    const int M = B_ * S_;  // 4096

    // 1) LN1 -> n1 (tf32)
    ln_kernel<<<M, 256>>>(x, g1, bl1, n1);

    // 2) Q, K, V projections
    {
        dim3 grid(D_ / BN, M / BM);
        mmagemm_kernel<<<grid, 256>>>((const uint32_t*)n1, Wq, bq, nullptr, q, M, D_, D_, 0, 0);
        mmagemm_kernel<<<grid, 256>>>((const uint32_t*)n1, Wk, bk, nullptr, k, M, D_, D_, 0, 0);
        mmagemm_kernel<<<grid, 256>>>((const uint32_t*)n1, Wv, bv, nullptr, v, M, D_, D_, 0, 0);
    }

    // 3) sparse attention -> o (tf32)
    {
        dim3 grid(S_ / QB, H_, B_);
        attn4_kernel<<<grid, 256, ATTN_SMEM>>>(q, k, v, mask, o);
    }

    // 4) output projection + residual -> x1 (fp32)
    {
        dim3 grid(D_ / BN, M / BM);
        mmagemm_kernel<<<grid, 256>>>((const uint32_t*)o, Wo, bo, x, x1, M, D_, D_, 0, 0);
    }

    // 5) LN2 -> n2 (tf32)
    ln_kernel<<<M, 256>>>(x1, g2, bl2, n2);

    // 6) FFN up + GELU -> ff (tf32)
    {
        dim3 grid(FF_ / BN, M / BM);
        mmagemm_kernel<<<grid, 256>>>((const uint32_t*)n2, W1, bf1, nullptr, ff, M, FF_, D_, 1, 1);
    }

    // 7) FFN down + residual -> out (fp32)
    {
        dim3 grid(D_ / BN, M / BM);
        mmagemm_kernel<<<grid, 256>>>((const uint32_t*)ff, W2, bf2, x1, out, M, D_, FF_, 0, 0);
    }
}

// round 15
// speedup vs baseline: 1.1359x; 1.0090x over previous
#include <cuda_runtime.h>
#include <math.h>
#include <stdint.h>

#define B_ 2
#define S_ 2048
#define D_ 1024
#define H_ 16
#define DK_ 64
#define FF_ 4096
#define NEG_ (-1000000000.0f)

// ---------------- scratch buffers ----------------
__device__ float g_n1[(size_t)B_ * S_ * D_];    // tf32 bits
__device__ float g_q [(size_t)B_ * S_ * D_];    // fp32
__device__ float g_k [(size_t)B_ * S_ * D_];    // fp32
__device__ float g_v [(size_t)B_ * S_ * D_];    // fp32
__device__ float g_o [(size_t)B_ * S_ * D_];    // tf32 bits
__device__ float g_x1[(size_t)B_ * S_ * D_];    // fp32
__device__ float g_n2[(size_t)B_ * S_ * D_];    // tf32 bits
__device__ float g_ff[(size_t)B_ * S_ * FF_];   // tf32 bits

__device__ __forceinline__ uint32_t f2tf32(float f) {
    uint32_t r; asm("cvt.rna.tf32.f32 %0, %1;" : "=r"(r) : "f"(f)); return r;
}

__device__ __forceinline__ void mma_tf32(float c[4], const uint32_t a[4], const uint32_t b[2]) {
    asm volatile(
        "mma.sync.aligned.m16n8k8.row.col.f32.tf32.tf32.f32 "
        "{%0,%1,%2,%3}, {%4,%5,%6,%7}, {%8,%9}, {%0,%1,%2,%3};"
        : "+f"(c[0]), "+f"(c[1]), "+f"(c[2]), "+f"(c[3])
        : "r"(a[0]), "r"(a[1]), "r"(a[2]), "r"(a[3]), "r"(b[0]), "r"(b[1]));
}

// ================= tf32 tensor-core GEMM (R13 champion, unchanged) ============
#define BM 128
#define BN 128
#define BK 16

__global__ __launch_bounds__(256) void mmagemm_kernel(const uint32_t* __restrict__ A,
                                                      const float* __restrict__ W,
                                                      const float* __restrict__ bias,
                                                      const float* __restrict__ res,
                                                      float* __restrict__ C,
                                                      int M, int N, int K, int act, int outtf)
{
    __shared__ alignas(128) char Asm[2 * 8192];
    __shared__ alignas(128) char Bsm[2 * 8192];

    const int tid = threadIdx.x;
    const int wid = tid >> 5, lane = tid & 31;
    const int row0 = blockIdx.y * BM;
    const int col0 = blockIdx.x * BN;

    const int m0w = (wid >> 2) * 64;
    const int n0w = (wid & 3) * 32;
    const int g16b = m0w >> 4;
    const int bg8 = n0w >> 3;

    const int ar = tid >> 2;
    const int ac = (tid & 3) << 2;
    const int lga = ar & 7;
    const int swa = (lga >> 1) & 3;
    const int abase = ((ac >> 3) * 8 + (ar >> 4)) * 512 +
                      ((((ac >> 2) & 1) * 2) + ((ar >> 3) & 1)) * 4;
    int aoff[4];
#pragma unroll
    for (int j = 0; j < 4; j++) aoff[j] = abase + (((lga * 4 + j) ^ swa) << 4);

    const int kq = tid >> 6;
    const int nn = tid & 63;
    int boff[2][2];
#pragma unroll
    for (int t = 0; t < 2; t++) {
        const int nv = nn + t * 64;
        const int g8 = nv >> 3;
        const int slot = (((nv & 7) * 4 + kq) ^ (g8 & 3));
#pragma unroll
        for (int kb = 0; kb < 2; kb++)
            boff[t][kb] = ((kb * 16 + g8) << 8) + slot * 8;
    }

    const int aslot = ((lane ^ ((lane >> 3) & 3)) << 4);

    float acc[4][4][4];
#pragma unroll
    for (int mi = 0; mi < 4; mi++)
#pragma unroll
        for (int ni = 0; ni < 4; ni++)
#pragma unroll
            for (int r = 0; r < 4; r++) acc[mi][ni][r] = 0.f;

    const int NC = K / BK;

    // prologue: chunk 0 -> buffer 0
    {
        const uint4 av0 = *reinterpret_cast<const uint4*>(A + (size_t)(row0 + ar) * K + ac);
        const uint4 av1 = *reinterpret_cast<const uint4*>(A + (size_t)(row0 + 64 + ar) * K + ac);
        const uint32_t a0[4] = {av0.x, av0.y, av0.z, av0.w};
        const uint32_t a1[4] = {av1.x, av1.y, av1.z, av1.w};
#pragma unroll
        for (int j = 0; j < 4; j++) {
            *reinterpret_cast<uint32_t*>(Asm + aoff[j]) = a0[j];
            *reinterpret_cast<uint32_t*>(Asm + aoff[j] + 2048) = a1[j];
        }
        float wreg[2][4];
#pragma unroll
        for (int t = 0; t < 2; t++)
#pragma unroll
            for (int s = 0; s < 4; s++)
                wreg[t][s] = W[(size_t)(kq + s * 4) * N + col0 + nn + t * 64];
#pragma unroll
        for (int t = 0; t < 2; t++)
#pragma unroll
            for (int kb = 0; kb < 2; kb++) {
                uint2 u = {f2tf32(wreg[t][kb * 2 + 0]), f2tf32(wreg[t][kb * 2 + 1])};
                *reinterpret_cast<uint2*>(Bsm + boff[t][kb]) = u;
            }
    }
    __syncthreads();

    for (int c = 0; c < NC; c++) {
        const int buf = c & 1;
        const char* Ab = Asm + buf * 8192;
        const char* Bb = Bsm + buf * 8192;

        uint4 av0, av1;
        float wreg[2][4];
        if (c + 1 < NC) {
            const int k0 = (c + 1) * BK;
            av0 = *reinterpret_cast<const uint4*>(A + (size_t)(row0 + ar) * K + k0 + ac);
            av1 = *reinterpret_cast<const uint4*>(A + (size_t)(row0 + 64 + ar) * K + k0 + ac);
#pragma unroll
            for (int t = 0; t < 2; t++)
#pragma unroll
                for (int s = 0; s < 4; s++)
                    wreg[t][s] = W[(size_t)(k0 + kq + s * 4) * N + col0 + nn + t * 64];
        }

#pragma unroll
        for (int kb = 0; kb < 2; kb++) {
            const char* Abk = Ab + (kb << 12);
            const char* Bbk = Bb + (kb << 12);
            uint4 afr[4];
            uint2 bfr[4];
#pragma unroll
            for (int mi = 0; mi < 4; mi++)
                afr[mi] = *reinterpret_cast<const uint4*>(Abk + ((g16b + mi) << 9) + aslot);
#pragma unroll
            for (int ni = 0; ni < 4; ni++) {
                const int g8 = bg8 + ni;
                bfr[ni] = *reinterpret_cast<const uint2*>(Bbk + (g8 << 8) + ((lane ^ (g8 & 3)) << 3));
            }
#pragma unroll
            for (int mi = 0; mi < 4; mi++)
#pragma unroll
                for (int ni = 0; ni < 4; ni++)
                    mma_tf32(acc[mi][ni],
                             reinterpret_cast<const uint32_t*>(&afr[mi]),
                             reinterpret_cast<const uint32_t*>(&bfr[ni]));
        }

        if (c + 1 < NC) {
            char* An = Asm + (buf ^ 1) * 8192;
            char* Bn = Bsm + (buf ^ 1) * 8192;
            const uint32_t a0[4] = {av0.x, av0.y, av0.z, av0.w};
            const uint32_t a1[4] = {av1.x, av1.y, av1.z, av1.w};
#pragma unroll
            for (int j = 0; j < 4; j++) {
                *reinterpret_cast<uint32_t*>(An + aoff[j]) = a0[j];
                *reinterpret_cast<uint32_t*>(An + aoff[j] + 2048) = a1[j];
            }
#pragma unroll
            for (int t = 0; t < 2; t++)
#pragma unroll
                for (int kb = 0; kb < 2; kb++) {
                    uint2 u = {f2tf32(wreg[t][kb * 2 + 0]), f2tf32(wreg[t][kb * 2 + 1])};
                    *reinterpret_cast<uint2*>(Bn + boff[t][kb]) = u;
                }
            __syncthreads();
        }
    }

    // epilogue
    const int lg = lane >> 2, lt = lane & 3;
#pragma unroll
    for (int mi = 0; mi < 4; mi++) {
#pragma unroll
        for (int half = 0; half < 2; half++) {
            const int r = row0 + m0w + mi * 16 + lg + half * 8;
#pragma unroll
            for (int ni = 0; ni < 4; ni++) {
                const int cc = col0 + n0w + ni * 8 + lt * 2;
                float2 o;
                o.x = acc[mi][ni][half * 2 + 0] + bias[cc];
                o.y = acc[mi][ni][half * 2 + 1] + bias[cc + 1];
                if (act == 1) {
                    o.x = 0.5f * o.x * (1.0f + erff(o.x * 0.70710678118654752f));
                    o.y = 0.5f * o.y * (1.0f + erff(o.y * 0.70710678118654752f));
                }
                if (res) {
                    const float2 rv = *reinterpret_cast<const float2*>(res + (size_t)r * N + cc);
                    o.x += rv.x; o.y += rv.y;
                }
                if (outtf) {
                    o.x = __uint_as_float(f2tf32(o.x));
                    o.y = __uint_as_float(f2tf32(o.y));
                }
                *reinterpret_cast<float2*>(C + (size_t)r * N + cc) = o;
            }
        }
    }
}

// ---------------- LayerNorm (emits tf32 bits) ----------------
__global__ __launch_bounds__(256) void ln_kernel(const float* __restrict__ x,
                                                 const float* __restrict__ g,
                                                 const float* __restrict__ b,
                                                 float* __restrict__ out)
{
    const int row = blockIdx.x;
    const float* xr = x + (size_t)row * D_;
    float* outr = out + (size_t)row * D_;
    const int tid = threadIdx.x;

    float4 v = reinterpret_cast<const float4*>(xr)[tid];
    float s = v.x + v.y + v.z + v.w;
    float ss = v.x * v.x + v.y * v.y + v.z * v.z + v.w * v.w;

    __shared__ float sh_s[8], sh_ss[8];
    for (int off = 16; off; off >>= 1) {
        s  += __shfl_xor_sync(0xffffffffu, s, off);
        ss += __shfl_xor_sync(0xffffffffu, ss, off);
    }
    const int wid = tid >> 5, lane = tid & 31;
    if (lane == 0) { sh_s[wid] = s; sh_ss[wid] = ss; }
    __syncthreads();
    if (wid == 0) {
        s  = (lane < 8) ? sh_s[lane]  : 0.f;
        ss = (lane < 8) ? sh_ss[lane] : 0.f;
        for (int off = 4; off; off >>= 1) {
            s  += __shfl_xor_sync(0xffffffffu, s, off);
            ss += __shfl_xor_sync(0xffffffffu, ss, off);
        }
        if (lane == 0) { sh_s[0] = s; sh_ss[0] = ss; }
    }
    __syncthreads();
    const float mu = sh_s[0] * (1.0f / D_);
    const float var = sh_ss[0] * (1.0f / D_) - mu * mu;
    const float rstd = rsqrtf(var + 1e-5f);

    float4 gv = reinterpret_cast<const float4*>(g)[tid];
    float4 bv = reinterpret_cast<const float4*>(b)[tid];
    uint4 o;
    o.x = f2tf32((v.x - mu) * rstd * gv.x + bv.x);
    o.y = f2tf32((v.y - mu) * rstd * gv.y + bv.y);
    o.z = f2tf32((v.z - mu) * rstd * gv.z + bv.z);
    o.w = f2tf32((v.w - mu) * rstd * gv.w + bv.w);
    reinterpret_cast<uint4*>(outr)[tid] = o;
}

// ====== sparse attention v5: two-pass softmax, 512 threads / 4 queries per warp
#define QB 64
#define KW 192
#define KP 68
#define VP 196
#define ATTN_T 512
#define ATTN_SMEM ((KW * KP + 64 * VP + 16 * 32) * 4)

__global__ __launch_bounds__(ATTN_T) void attn5_kernel(const float* __restrict__ Q,
                                                       const float* __restrict__ K,
                                                       const float* __restrict__ V,
                                                       const int* __restrict__ mask,
                                                       float* __restrict__ O)
{
    extern __shared__ float smattn[];
    float* Ks  = smattn;
    float* Vt  = smattn + KW * KP;
    float* psm = smattn + KW * KP + 64 * VP;

    const int qb0 = blockIdx.x * QB;
    const int h = blockIdx.y;
    const int b = blockIdx.z;
    const int tid = threadIdx.x;
    const int warp = tid >> 5, lane = tid & 31;
    const int base_row = qb0 - 128;

    for (int idx = tid; idx < KW * 64; idx += ATTN_T) {
        const int r = idx >> 6, d = idx & 63;
        const int j = base_row + r;
        float kv = 0.f, vv = 0.f;
        if (j >= 0) {
            const size_t g = ((size_t)(b * S_ + j)) * D_ + h * 64 + d;
            kv = K[g]; vv = V[g];
        }
        Ks[r * KP + d] = kv;
        Vt[d * VP + r] = vv;
    }
    __syncthreads();

    float* pb = psm + warp * 32;

#pragma unroll 1
    for (int qi = 0; qi < 4; qi++) {
        const int o_in_blk = warp * 4 + qi;
        const int i = qb0 + o_in_blk;
        const float4* q4 = reinterpret_cast<const float4*>(Q + ((size_t)(b * S_ + i)) * D_ + h * 64);
        float4 rq[16];
#pragma unroll
        for (int d = 0; d < 16; d++) rq[d] = __ldg(q4 + d);
        const int* mrow = mask + (size_t)i * S_;
        const int u0 = o_in_blk >> 5;

        // ---- pass 1a: strided score (lane l -> key j = i-256-128l) ----
        float s_str = -INFINITY;
        {
            const int j = i - 256 - 128 * lane;
            if (j >= 0) {
                const float4* kr = reinterpret_cast<const float4*>(K + ((size_t)(b * S_ + j)) * D_ + h * 64);
                float dv = 0.f;
#pragma unroll
                for (int d = 0; d < 16; d++) {
                    const float4 kv = __ldg(kr + d);
                    dv = fmaf(rq[d].x, kv.x, dv);
                    dv = fmaf(rq[d].y, kv.y, dv);
                    dv = fmaf(rq[d].z, kv.z, dv);
                    dv = fmaf(rq[d].w, kv.w, dv);
                }
                s_str = dv * 0.125f;
                if (mrow[j] == 0) s_str = NEG_;
            }
        }

        // ---- pass 1b: local segment scores (independent) ----
        float s_loc[5];
#pragma unroll
        for (int t = 0; t < 5; t++) {
            const int koff = (u0 + t) * 32;
            const int j = base_row + koff + lane;
            float s = -INFINITY;
            if (j >= 0 && j >= i - 128 && j <= i) {
                const float4* kr = reinterpret_cast<const float4*>(Ks + (koff + lane) * KP);
                float dv = 0.f;
#pragma unroll
                for (int d = 0; d < 16; d++) {
                    const float4 kv = kr[d];
                    dv = fmaf(rq[d].x, kv.x, dv);
                    dv = fmaf(rq[d].y, kv.y, dv);
                    dv = fmaf(rq[d].z, kv.z, dv);
                    dv = fmaf(rq[d].w, kv.w, dv);
                }
                s = dv * 0.125f;
                if (mrow[j] == 0) s = NEG_;
            }
            s_loc[t] = s;
        }

        // ---- single max reduce (m always finite: key j=i is in-range) ----
        float m = s_str;
#pragma unroll
        for (int t = 0; t < 5; t++) m = fmaxf(m, s_loc[t]);
        for (int off = 16; off; off >>= 1)
            m = fmaxf(m, __shfl_xor_sync(0xffffffffu, m, off));

        // ---- probs + single sum reduce ----
        const float p_str = __expf(s_str - m);
        float p_loc[5];
        float l = p_str;
#pragma unroll
        for (int t = 0; t < 5; t++) { p_loc[t] = __expf(s_loc[t] - m); l += p_loc[t]; }
        for (int off = 16; off; off >>= 1)
            l += __shfl_xor_sync(0xffffffffu, l, off);

        // ---- pass 2: P.V (unscaled) ----
        float acc0 = 0.f, acc1 = 0.f;
#pragma unroll 1
        for (int t = 0; t < 5; t++) {
            const int koff = (u0 + t) * 32;
            __syncwarp();
            pb[lane] = p_loc[t];
            __syncwarp();
            const float4* pv4 = reinterpret_cast<const float4*>(pb);
            const float4* v0 = reinterpret_cast<const float4*>(Vt + lane * VP + koff);
            const float4* v1 = reinterpret_cast<const float4*>(Vt + (lane + 32) * VP + koff);
#pragma unroll
            for (int kk = 0; kk < 8; kk++) {
                const float4 pp = pv4[kk];
                const float4 va = v0[kk];
                const float4 vb = v1[kk];
                acc0 = fmaf(pp.x, va.x, acc0);
                acc0 = fmaf(pp.y, va.y, acc0);
                acc0 = fmaf(pp.z, va.z, acc0);
                acc0 = fmaf(pp.w, va.w, acc0);
                acc1 = fmaf(pp.x, vb.x, acc1);
                acc1 = fmaf(pp.y, vb.y, acc1);
                acc1 = fmaf(pp.z, vb.z, acc1);
                acc1 = fmaf(pp.w, vb.w, acc1);
            }
        }
        // strided P.V
        const int cnt = (i >= 256) ? (((i - 256) >> 7) + 1) : 0;
        for (int l2 = 0; l2 < cnt; l2++) {
            const float pv = __shfl_sync(0xffffffffu, p_str, l2);
            const int j2 = i - 256 - 128 * l2;
            const float* vr = V + ((size_t)(b * S_ + j2)) * D_ + h * 64;
            acc0 = fmaf(pv, __ldg(vr + lane), acc0);
            acc1 = fmaf(pv, __ldg(vr + lane + 32), acc1);
        }

        const float inv = 1.0f / l;
        float* orow = O + ((size_t)(b * S_ + i)) * D_ + h * 64;
        orow[lane]      = __uint_as_float(f2tf32(acc0 * inv));
        orow[lane + 32] = __uint_as_float(f2tf32(acc1 * inv));
    }
}

// ---------------- host launcher ----------------
extern "C" void kernel_launch(void* const* d_in, const int* in_sizes, int n_in,
                              void* d_out, int out_size)
{
    (void)in_sizes; (void)n_in; (void)out_size;
    const float* x    = (const float*)d_in[0];
    const int*   mask = (const int*)  d_in[1];
    const float* Wq = (const float*)d_in[2];  const float* bq = (const float*)d_in[3];
    const float* Wk = (const float*)d_in[4];  const float* bk = (const float*)d_in[5];
    const float* Wv = (const float*)d_in[6];  const float* bv = (const float*)d_in[7];
    const float* Wo = (const float*)d_in[8];  const float* bo = (const float*)d_in[9];
    const float* W1 = (const float*)d_in[10]; const float* bf1 = (const float*)d_in[11];
    const float* W2 = (const float*)d_in[12]; const float* bf2 = (const float*)d_in[13];
    const float* g1 = (const float*)d_in[14]; const float* bl1 = (const float*)d_in[15];
    const float* g2 = (const float*)d_in[16]; const float* bl2 = (const float*)d_in[17];
    float* out = (float*)d_out;

    float *n1, *q, *k, *v, *o, *x1, *n2, *ff;
    cudaGetSymbolAddress((void**)&n1, g_n1);
    cudaGetSymbolAddress((void**)&q,  g_q);
    cudaGetSymbolAddress((void**)&k,  g_k);
    cudaGetSymbolAddress((void**)&v,  g_v);
    cudaGetSymbolAddress((void**)&o,  g_o);
    cudaGetSymbolAddress((void**)&x1, g_x1);
    cudaGetSymbolAddress((void**)&n2, g_n2);
    cudaGetSymbolAddress((void**)&ff, g_ff);

    cudaFuncSetAttribute(attn5_kernel, cudaFuncAttributeMaxDynamicSharedMemorySize, ATTN_SMEM);

    const int M = B_ * S_;  // 4096

    // 1) LN1 -> n1 (tf32)
    ln_kernel<<<M, 256>>>(x, g1, bl1, n1);

    // 2) Q, K, V projections
    {
        dim3 grid(D_ / BN, M / BM);
        mmagemm_kernel<<<grid, 256>>>((const uint32_t*)n1, Wq, bq, nullptr, q, M, D_, D_, 0, 0);
        mmagemm_kernel<<<grid, 256>>>((const uint32_t*)n1, Wk, bk, nullptr, k, M, D_, D_, 0, 0);
        mmagemm_kernel<<<grid, 256>>>((const uint32_t*)n1, Wv, bv, nullptr, v, M, D_, D_, 0, 0);
    }

    // 3) sparse attention -> o (tf32)
    {
        dim3 grid(S_ / QB, H_, B_);
        attn5_kernel<<<grid, ATTN_T, ATTN_SMEM>>>(q, k, v, mask, o);
    }

    // 4) output projection + residual -> x1 (fp32)
    {
        dim3 grid(D_ / BN, M / BM);
        mmagemm_kernel<<<grid, 256>>>((const uint32_t*)o, Wo, bo, x, x1, M, D_, D_, 0, 0);
    }

    // 5) LN2 -> n2 (tf32)
    ln_kernel<<<M, 256>>>(x1, g2, bl2, n2);

    // 6) FFN up + GELU -> ff (tf32)
    {
        dim3 grid(FF_ / BN, M / BM);
        mmagemm_kernel<<<grid, 256>>>((const uint32_t*)n2, W1, bf1, nullptr, ff, M, FF_, D_, 1, 1);
    }

    // 7) FFN down + residual -> out (fp32)
    {
        dim3 grid(D_ / BN, M / BM);
        mmagemm_kernel<<<grid, 256>>>((const uint32_t*)ff, W2, bf2, x1, out, M, D_, FF_, 0, 0);
    }
}

// round 16
// speedup vs baseline: 1.1365x; 1.0005x over previous
#include <cuda_runtime.h>
#include <math.h>
#include <stdint.h>

#define B_ 2
#define S_ 2048
#define D_ 1024
#define H_ 16
#define DK_ 64
#define FF_ 4096
#define NEG_ (-1000000000.0f)

// ---------------- scratch buffers ----------------
__device__ float g_n1[(size_t)B_ * S_ * D_];    // tf32 bits
__device__ float g_q [(size_t)B_ * S_ * D_];    // fp32
__device__ float g_k [(size_t)B_ * S_ * D_];    // fp32
__device__ float g_v [(size_t)B_ * S_ * D_];    // fp32
__device__ float g_o [(size_t)B_ * S_ * D_];    // tf32 bits
__device__ float g_x1[(size_t)B_ * S_ * D_];    // fp32
__device__ float g_n2[(size_t)B_ * S_ * D_];    // tf32 bits
__device__ float g_ff[(size_t)B_ * S_ * FF_];   // tf32 bits

__device__ __forceinline__ uint32_t f2tf32(float f) {
    uint32_t r; asm("cvt.rna.tf32.f32 %0, %1;" : "=r"(r) : "f"(f)); return r;
}

__device__ __forceinline__ void mma_tf32(float c[4], const uint32_t a[4], const uint32_t b[2]) {
    asm volatile(
        "mma.sync.aligned.m16n8k8.row.col.f32.tf32.tf32.f32 "
        "{%0,%1,%2,%3}, {%4,%5,%6,%7}, {%8,%9}, {%0,%1,%2,%3};"
        : "+f"(c[0]), "+f"(c[1]), "+f"(c[2]), "+f"(c[3])
        : "r"(a[0]), "r"(a[1]), "r"(a[2]), "r"(a[3]), "r"(b[0]), "r"(b[1]));
}

// ================= tf32 tensor-core GEMM (R13 structure; bias-hoisted epilogue)
#define BM 128
#define BN 128
#define BK 16

__global__ __launch_bounds__(256) void mmagemm_kernel(const uint32_t* __restrict__ A,
                                                      const float* __restrict__ W,
                                                      const float* __restrict__ bias,
                                                      const float* __restrict__ res,
                                                      float* __restrict__ C,
                                                      int M, int N, int K, int act, int outtf)
{
    __shared__ alignas(128) char Asm[2 * 8192];
    __shared__ alignas(128) char Bsm[2 * 8192];

    const int tid = threadIdx.x;
    const int wid = tid >> 5, lane = tid & 31;
    const int row0 = blockIdx.y * BM;
    const int col0 = blockIdx.x * BN;

    const int m0w = (wid >> 2) * 64;
    const int n0w = (wid & 3) * 32;
    const int g16b = m0w >> 4;
    const int bg8 = n0w >> 3;

    const int ar = tid >> 2;
    const int ac = (tid & 3) << 2;
    const int lga = ar & 7;
    const int swa = (lga >> 1) & 3;
    const int abase = ((ac >> 3) * 8 + (ar >> 4)) * 512 +
                      ((((ac >> 2) & 1) * 2) + ((ar >> 3) & 1)) * 4;
    int aoff[4];
#pragma unroll
    for (int j = 0; j < 4; j++) aoff[j] = abase + (((lga * 4 + j) ^ swa) << 4);

    const int kq = tid >> 6;
    const int nn = tid & 63;
    int boff[2][2];
#pragma unroll
    for (int t = 0; t < 2; t++) {
        const int nv = nn + t * 64;
        const int g8 = nv >> 3;
        const int slot = (((nv & 7) * 4 + kq) ^ (g8 & 3));
#pragma unroll
        for (int kb = 0; kb < 2; kb++)
            boff[t][kb] = ((kb * 16 + g8) << 8) + slot * 8;
    }

    const int aslot = ((lane ^ ((lane >> 3) & 3)) << 4);

    float acc[4][4][4];
#pragma unroll
    for (int mi = 0; mi < 4; mi++)
#pragma unroll
        for (int ni = 0; ni < 4; ni++)
#pragma unroll
            for (int r = 0; r < 4; r++) acc[mi][ni][r] = 0.f;

    const int NC = K / BK;

    // prologue: chunk 0 -> buffer 0
    {
        const uint4 av0 = *reinterpret_cast<const uint4*>(A + (size_t)(row0 + ar) * K + ac);
        const uint4 av1 = *reinterpret_cast<const uint4*>(A + (size_t)(row0 + 64 + ar) * K + ac);
        const uint32_t a0[4] = {av0.x, av0.y, av0.z, av0.w};
        const uint32_t a1[4] = {av1.x, av1.y, av1.z, av1.w};
#pragma unroll
        for (int j = 0; j < 4; j++) {
            *reinterpret_cast<uint32_t*>(Asm + aoff[j]) = a0[j];
            *reinterpret_cast<uint32_t*>(Asm + aoff[j] + 2048) = a1[j];
        }
        float wreg[2][4];
#pragma unroll
        for (int t = 0; t < 2; t++)
#pragma unroll
            for (int s = 0; s < 4; s++)
                wreg[t][s] = W[(size_t)(kq + s * 4) * N + col0 + nn + t * 64];
#pragma unroll
        for (int t = 0; t < 2; t++)
#pragma unroll
            for (int kb = 0; kb < 2; kb++) {
                uint2 u = {f2tf32(wreg[t][kb * 2 + 0]), f2tf32(wreg[t][kb * 2 + 1])};
                *reinterpret_cast<uint2*>(Bsm + boff[t][kb]) = u;
            }
    }
    __syncthreads();

    for (int c = 0; c < NC; c++) {
        const int buf = c & 1;
        const char* Ab = Asm + buf * 8192;
        const char* Bb = Bsm + buf * 8192;

        uint4 av0, av1;
        float wreg[2][4];
        if (c + 1 < NC) {
            const int k0 = (c + 1) * BK;
            av0 = *reinterpret_cast<const uint4*>(A + (size_t)(row0 + ar) * K + k0 + ac);
            av1 = *reinterpret_cast<const uint4*>(A + (size_t)(row0 + 64 + ar) * K + k0 + ac);
#pragma unroll
            for (int t = 0; t < 2; t++)
#pragma unroll
                for (int s = 0; s < 4; s++)
                    wreg[t][s] = W[(size_t)(k0 + kq + s * 4) * N + col0 + nn + t * 64];
        }

#pragma unroll
        for (int kb = 0; kb < 2; kb++) {
            const char* Abk = Ab + (kb << 12);
            const char* Bbk = Bb + (kb << 12);
            uint4 afr[4];
            uint2 bfr[4];
#pragma unroll
            for (int mi = 0; mi < 4; mi++)
                afr[mi] = *reinterpret_cast<const uint4*>(Abk + ((g16b + mi) << 9) + aslot);
#pragma unroll
            for (int ni = 0; ni < 4; ni++) {
                const int g8 = bg8 + ni;
                bfr[ni] = *reinterpret_cast<const uint2*>(Bbk + (g8 << 8) + ((lane ^ (g8 & 3)) << 3));
            }
#pragma unroll
            for (int mi = 0; mi < 4; mi++)
#pragma unroll
                for (int ni = 0; ni < 4; ni++)
                    mma_tf32(acc[mi][ni],
                             reinterpret_cast<const uint32_t*>(&afr[mi]),
                             reinterpret_cast<const uint32_t*>(&bfr[ni]));
        }

        if (c + 1 < NC) {
            char* An = Asm + (buf ^ 1) * 8192;
            char* Bn = Bsm + (buf ^ 1) * 8192;
            const uint32_t a0[4] = {av0.x, av0.y, av0.z, av0.w};
            const uint32_t a1[4] = {av1.x, av1.y, av1.z, av1.w};
#pragma unroll
            for (int j = 0; j < 4; j++) {
                *reinterpret_cast<uint32_t*>(An + aoff[j]) = a0[j];
                *reinterpret_cast<uint32_t*>(An + aoff[j] + 2048) = a1[j];
            }
#pragma unroll
            for (int t = 0; t < 2; t++)
#pragma unroll
                for (int kb = 0; kb < 2; kb++) {
                    uint2 u = {f2tf32(wreg[t][kb * 2 + 0]), f2tf32(wreg[t][kb * 2 + 1])};
                    *reinterpret_cast<uint2*>(Bn + boff[t][kb]) = u;
                }
            __syncthreads();
        }
    }

    // epilogue (bias hoisted: cc depends only on ni)
    const int lg = lane >> 2, lt = lane & 3;
    float2 bias2[4];
#pragma unroll
    for (int ni = 0; ni < 4; ni++)
        bias2[ni] = *reinterpret_cast<const float2*>(bias + col0 + n0w + ni * 8 + lt * 2);
#pragma unroll
    for (int mi = 0; mi < 4; mi++) {
#pragma unroll
        for (int half = 0; half < 2; half++) {
            const int r = row0 + m0w + mi * 16 + lg + half * 8;
#pragma unroll
            for (int ni = 0; ni < 4; ni++) {
                const int cc = col0 + n0w + ni * 8 + lt * 2;
                float2 o;
                o.x = acc[mi][ni][half * 2 + 0] + bias2[ni].x;
                o.y = acc[mi][ni][half * 2 + 1] + bias2[ni].y;
                if (act == 1) {
                    o.x = 0.5f * o.x * (1.0f + erff(o.x * 0.70710678118654752f));
                    o.y = 0.5f * o.y * (1.0f + erff(o.y * 0.70710678118654752f));
                }
                if (res) {
                    const float2 rv = *reinterpret_cast<const float2*>(res + (size_t)r * N + cc);
                    o.x += rv.x; o.y += rv.y;
                }
                if (outtf) {
                    o.x = __uint_as_float(f2tf32(o.x));
                    o.y = __uint_as_float(f2tf32(o.y));
                }
                *reinterpret_cast<float2*>(C + (size_t)r * N + cc) = o;
            }
        }
    }
}

// ---------------- LayerNorm v2: warp-per-row, no block barriers ---------------
// 256 threads = 8 warps = 8 rows per CTA; lane holds 8 float4 (32 elems).
__global__ __launch_bounds__(256) void ln_kernel(const float* __restrict__ x,
                                                 const float* __restrict__ g,
                                                 const float* __restrict__ b,
                                                 float* __restrict__ out)
{
    const int warp = threadIdx.x >> 5, lane = threadIdx.x & 31;
    const int row = blockIdx.x * 8 + warp;
    const float4* xr = reinterpret_cast<const float4*>(x + (size_t)row * D_);
    uint4* outr = reinterpret_cast<uint4*>(out + (size_t)row * D_);
    const float4* g4 = reinterpret_cast<const float4*>(g);
    const float4* b4 = reinterpret_cast<const float4*>(b);

    float4 v[8];
#pragma unroll
    for (int k = 0; k < 8; k++) v[k] = xr[k * 32 + lane];

    float s = 0.f, ss = 0.f;
#pragma unroll
    for (int k = 0; k < 8; k++) {
        s  += v[k].x + v[k].y + v[k].z + v[k].w;
        ss += v[k].x * v[k].x + v[k].y * v[k].y + v[k].z * v[k].z + v[k].w * v[k].w;
    }
    for (int off = 16; off; off >>= 1) {
        s  += __shfl_xor_sync(0xffffffffu, s, off);
        ss += __shfl_xor_sync(0xffffffffu, ss, off);
    }
    const float mu = s * (1.0f / D_);
    const float var = ss * (1.0f / D_) - mu * mu;
    const float rstd = rsqrtf(var + 1e-5f);

#pragma unroll
    for (int k = 0; k < 8; k++) {
        const float4 gv = g4[k * 32 + lane];
        const float4 bv = b4[k * 32 + lane];
        uint4 o;
        o.x = f2tf32((v[k].x - mu) * rstd * gv.x + bv.x);
        o.y = f2tf32((v[k].y - mu) * rstd * gv.y + bv.y);
        o.z = f2tf32((v[k].z - mu) * rstd * gv.z + bv.z);
        o.w = f2tf32((v[k].w - mu) * rstd * gv.w + bv.w);
        outr[k * 32 + lane] = o;
    }
}

// ====== sparse attention v5 (R15 champion, unchanged) ======
#define QB 64
#define KW 192
#define KP 68
#define VP 196
#define ATTN_T 512
#define ATTN_SMEM ((KW * KP + 64 * VP + 16 * 32) * 4)

__global__ __launch_bounds__(ATTN_T) void attn5_kernel(const float* __restrict__ Q,
                                                       const float* __restrict__ K,
                                                       const float* __restrict__ V,
                                                       const int* __restrict__ mask,
                                                       float* __restrict__ O)
{
    extern __shared__ float smattn[];
    float* Ks  = smattn;
    float* Vt  = smattn + KW * KP;
    float* psm = smattn + KW * KP + 64 * VP;

    const int qb0 = blockIdx.x * QB;
    const int h = blockIdx.y;
    const int b = blockIdx.z;
    const int tid = threadIdx.x;
    const int warp = tid >> 5, lane = tid & 31;
    const int base_row = qb0 - 128;

    for (int idx = tid; idx < KW * 64; idx += ATTN_T) {
        const int r = idx >> 6, d = idx & 63;
        const int j = base_row + r;
        float kv = 0.f, vv = 0.f;
        if (j >= 0) {
            const size_t g = ((size_t)(b * S_ + j)) * D_ + h * 64 + d;
            kv = K[g]; vv = V[g];
        }
        Ks[r * KP + d] = kv;
        Vt[d * VP + r] = vv;
    }
    __syncthreads();

    float* pb = psm + warp * 32;

#pragma unroll 1
    for (int qi = 0; qi < 4; qi++) {
        const int o_in_blk = warp * 4 + qi;
        const int i = qb0 + o_in_blk;
        const float4* q4 = reinterpret_cast<const float4*>(Q + ((size_t)(b * S_ + i)) * D_ + h * 64);
        float4 rq[16];
#pragma unroll
        for (int d = 0; d < 16; d++) rq[d] = __ldg(q4 + d);
        const int* mrow = mask + (size_t)i * S_;
        const int u0 = o_in_blk >> 5;

        float s_str = -INFINITY;
        {
            const int j = i - 256 - 128 * lane;
            if (j >= 0) {
                const float4* kr = reinterpret_cast<const float4*>(K + ((size_t)(b * S_ + j)) * D_ + h * 64);
                float dv = 0.f;
#pragma unroll
                for (int d = 0; d < 16; d++) {
                    const float4 kv = __ldg(kr + d);
                    dv = fmaf(rq[d].x, kv.x, dv);
                    dv = fmaf(rq[d].y, kv.y, dv);
                    dv = fmaf(rq[d].z, kv.z, dv);
                    dv = fmaf(rq[d].w, kv.w, dv);
                }
                s_str = dv * 0.125f;
                if (mrow[j] == 0) s_str = NEG_;
            }
        }

        float s_loc[5];
#pragma unroll
        for (int t = 0; t < 5; t++) {
            const int koff = (u0 + t) * 32;
            const int j = base_row + koff + lane;
            float s = -INFINITY;
            if (j >= 0 && j >= i - 128 && j <= i) {
                const float4* kr = reinterpret_cast<const float4*>(Ks + (koff + lane) * KP);
                float dv = 0.f;
#pragma unroll
                for (int d = 0; d < 16; d++) {
                    const float4 kv = kr[d];
                    dv = fmaf(rq[d].x, kv.x, dv);
                    dv = fmaf(rq[d].y, kv.y, dv);
                    dv = fmaf(rq[d].z, kv.z, dv);
                    dv = fmaf(rq[d].w, kv.w, dv);
                }
                s = dv * 0.125f;
                if (mrow[j] == 0) s = NEG_;
            }
            s_loc[t] = s;
        }

        float m = s_str;
#pragma unroll
        for (int t = 0; t < 5; t++) m = fmaxf(m, s_loc[t]);
        for (int off = 16; off; off >>= 1)
            m = fmaxf(m, __shfl_xor_sync(0xffffffffu, m, off));

        const float p_str = __expf(s_str - m);
        float p_loc[5];
        float l = p_str;
#pragma unroll
        for (int t = 0; t < 5; t++) { p_loc[t] = __expf(s_loc[t] - m); l += p_loc[t]; }
        for (int off = 16; off; off >>= 1)
            l += __shfl_xor_sync(0xffffffffu, l, off);

        float acc0 = 0.f, acc1 = 0.f;
#pragma unroll 1
        for (int t = 0; t < 5; t++) {
            const int koff = (u0 + t) * 32;
            __syncwarp();
            pb[lane] = p_loc[t];
            __syncwarp();
            const float4* pv4 = reinterpret_cast<const float4*>(pb);
            const float4* v0 = reinterpret_cast<const float4*>(Vt + lane * VP + koff);
            const float4* v1 = reinterpret_cast<const float4*>(Vt + (lane + 32) * VP + koff);
#pragma unroll
            for (int kk = 0; kk < 8; kk++) {
                const float4 pp = pv4[kk];
                const float4 va = v0[kk];
                const float4 vb = v1[kk];
                acc0 = fmaf(pp.x, va.x, acc0);
                acc0 = fmaf(pp.y, va.y, acc0);
                acc0 = fmaf(pp.z, va.z, acc0);
                acc0 = fmaf(pp.w, va.w, acc0);
                acc1 = fmaf(pp.x, vb.x, acc1);
                acc1 = fmaf(pp.y, vb.y, acc1);
                acc1 = fmaf(pp.z, vb.z, acc1);
                acc1 = fmaf(pp.w, vb.w, acc1);
            }
        }
        const int cnt = (i >= 256) ? (((i - 256) >> 7) + 1) : 0;
        for (int l2 = 0; l2 < cnt; l2++) {
            const float pv = __shfl_sync(0xffffffffu, p_str, l2);
            const int j2 = i - 256 - 128 * l2;
            const float* vr = V + ((size_t)(b * S_ + j2)) * D_ + h * 64;
            acc0 = fmaf(pv, __ldg(vr + lane), acc0);
            acc1 = fmaf(pv, __ldg(vr + lane + 32), acc1);
        }

        const float inv = 1.0f / l;
        float* orow = O + ((size_t)(b * S_ + i)) * D_ + h * 64;
        orow[lane]      = __uint_as_float(f2tf32(acc0 * inv));
        orow[lane + 32] = __uint_as_float(f2tf32(acc1 * inv));
    }
}

// ---------------- host launcher ----------------
extern "C" void kernel_launch(void* const* d_in, const int* in_sizes, int n_in,
                              void* d_out, int out_size)
{
    (void)in_sizes; (void)n_in; (void)out_size;
    const float* x    = (const float*)d_in[0];
    const int*   mask = (const int*)  d_in[1];
    const float* Wq = (const float*)d_in[2];  const float* bq = (const float*)d_in[3];
    const float* Wk = (const float*)d_in[4];  const float* bk = (const float*)d_in[5];
    const float* Wv = (const float*)d_in[6];  const float* bv = (const float*)d_in[7];
    const float* Wo = (const float*)d_in[8];  const float* bo = (const float*)d_in[9];
    const float* W1 = (const float*)d_in[10]; const float* bf1 = (const float*)d_in[11];
    const float* W2 = (const float*)d_in[12]; const float* bf2 = (const float*)d_in[13];
    const float* g1 = (const float*)d_in[14]; const float* bl1 = (const float*)d_in[15];
    const float* g2 = (const float*)d_in[16]; const float* bl2 = (const float*)d_in[17];
    float* out = (float*)d_out;

    float *n1, *q, *k, *v, *o, *x1, *n2, *ff;
    cudaGetSymbolAddress((void**)&n1, g_n1);
    cudaGetSymbolAddress((void**)&q,  g_q);
    cudaGetSymbolAddress((void**)&k,  g_k);
    cudaGetSymbolAddress((void**)&v,  g_v);
    cudaGetSymbolAddress((void**)&o,  g_o);
    cudaGetSymbolAddress((void**)&x1, g_x1);
    cudaGetSymbolAddress((void**)&n2, g_n2);
    cudaGetSymbolAddress((void**)&ff, g_ff);

    cudaFuncSetAttribute(attn5_kernel, cudaFuncAttributeMaxDynamicSharedMemorySize, ATTN_SMEM);

    const int M = B_ * S_;  // 4096

    // 1) LN1 -> n1 (tf32)
    ln_kernel<<<M / 8, 256>>>(x, g1, bl1, n1);

    // 2) Q, K, V projections
    {
        dim3 grid(D_ / BN, M / BM);
        mmagemm_kernel<<<grid, 256>>>((const uint32_t*)n1, Wq, bq, nullptr, q, M, D_, D_, 0, 0);
        mmagemm_kernel<<<grid, 256>>>((const uint32_t*)n1, Wk, bk, nullptr, k, M, D_, D_, 0, 0);
        mmagemm_kernel<<<grid, 256>>>((const uint32_t*)n1, Wv, bv, nullptr, v, M, D_, D_, 0, 0);
    }

    // 3) sparse attention -> o (tf32)
    {
        dim3 grid(S_ / QB, H_, B_);
        attn5_kernel<<<grid, ATTN_T, ATTN_SMEM>>>(q, k, v, mask, o);
    }

    // 4) output projection + residual -> x1 (fp32)
    {
        dim3 grid(D_ / BN, M / BM);
        mmagemm_kernel<<<grid, 256>>>((const uint32_t*)o, Wo, bo, x, x1, M, D_, D_, 0, 0);
    }

    // 5) LN2 -> n2 (tf32)
    ln_kernel<<<M / 8, 256>>>(x1, g2, bl2, n2);

    // 6) FFN up + GELU -> ff (tf32)
    {
        dim3 grid(FF_ / BN, M / BM);
        mmagemm_kernel<<<grid, 256>>>((const uint32_t*)n2, W1, bf1, nullptr, ff, M, FF_, D_, 1, 1);
    }

    // 7) FFN down + residual -> out (fp32)
    {
        dim3 grid(D_ / BN, M / BM);
        mmagemm_kernel<<<grid, 256>>>((const uint32_t*)ff, W2, bf2, x1, out, M, D_, FF_, 0, 0);
    }
}

// round 17
// speedup vs baseline: 1.1368x; 1.0003x over previous
#include <cuda_runtime.h>
#include <math.h>
#include <stdint.h>

#define B_ 2
#define S_ 2048
#define D_ 1024
#define H_ 16
#define DK_ 64
#define FF_ 4096
#define NEG_ (-1000000000.0f)

// ---------------- scratch buffers ----------------
__device__ float g_n1[(size_t)B_ * S_ * D_];    // tf32 bits
__device__ float g_q [(size_t)B_ * S_ * D_];    // fp32
__device__ float g_k [(size_t)B_ * S_ * D_];    // fp32
__device__ float g_v [(size_t)B_ * S_ * D_];    // fp32
__device__ float g_o [(size_t)B_ * S_ * D_];    // tf32 bits
__device__ float g_x1[(size_t)B_ * S_ * D_];    // fp32
__device__ float g_n2[(size_t)B_ * S_ * D_];    // tf32 bits
__device__ float g_ff[(size_t)B_ * S_ * FF_];   // tf32 bits
// pointer tables for batched-z GEMM (filled by a tiny device-side init kernel)
__device__ const float* g_Wtab[3];
__device__ const float* g_btab[3];
__device__ float* g_Ctab[3];

__device__ __forceinline__ uint32_t f2tf32(float f) {
    uint32_t r; asm("cvt.rna.tf32.f32 %0, %1;" : "=r"(r) : "f"(f)); return r;
}

__device__ __forceinline__ void mma_tf32(float c[4], const uint32_t a[4], const uint32_t b[2]) {
    asm volatile(
        "mma.sync.aligned.m16n8k8.row.col.f32.tf32.tf32.f32 "
        "{%0,%1,%2,%3}, {%4,%5,%6,%7}, {%8,%9}, {%0,%1,%2,%3};"
        : "+f"(c[0]), "+f"(c[1]), "+f"(c[2]), "+f"(c[3])
        : "r"(a[0]), "r"(a[1]), "r"(a[2]), "r"(a[3]), "r"(b[0]), "r"(b[1]));
}

// set pointer tables (single thread; graph-capturable)
__global__ void set_tabs_kernel(const float* W0, const float* W1p, const float* W2p,
                                const float* b0, const float* b1p, const float* b2p,
                                float* C0, float* C1p, float* C2p)
{
    g_Wtab[0] = W0; g_Wtab[1] = W1p; g_Wtab[2] = W2p;
    g_btab[0] = b0; g_btab[1] = b1p; g_btab[2] = b2p;
    g_Ctab[0] = C0; g_Ctab[1] = C1p; g_Ctab[2] = C2p;
}

// ================= tf32 tensor-core GEMM (R13 structure) ======================
#define BM 128
#define BN 128
#define BK 16

// core body shared by both entry points
__device__ __forceinline__ void gemm_body(const uint32_t* __restrict__ A,
                                          const float* __restrict__ W,
                                          const float* __restrict__ bias,
                                          const float* __restrict__ res,
                                          float* __restrict__ C,
                                          int M, int N, int K, int act, int outtf)
{
    __shared__ alignas(128) char Asm[2 * 8192];
    __shared__ alignas(128) char Bsm[2 * 8192];

    const int tid = threadIdx.x;
    const int wid = tid >> 5, lane = tid & 31;
    const int row0 = blockIdx.y * BM;
    const int col0 = blockIdx.x * BN;

    const int m0w = (wid >> 2) * 64;
    const int n0w = (wid & 3) * 32;
    const int g16b = m0w >> 4;
    const int bg8 = n0w >> 3;

    const int ar = tid >> 2;
    const int ac = (tid & 3) << 2;
    const int lga = ar & 7;
    const int swa = (lga >> 1) & 3;
    const int abase = ((ac >> 3) * 8 + (ar >> 4)) * 512 +
                      ((((ac >> 2) & 1) * 2) + ((ar >> 3) & 1)) * 4;
    int aoff[4];
#pragma unroll
    for (int j = 0; j < 4; j++) aoff[j] = abase + (((lga * 4 + j) ^ swa) << 4);

    const int kq = tid >> 6;
    const int nn = tid & 63;
    int boff[2][2];
#pragma unroll
    for (int t = 0; t < 2; t++) {
        const int nv = nn + t * 64;
        const int g8 = nv >> 3;
        const int slot = (((nv & 7) * 4 + kq) ^ (g8 & 3));
#pragma unroll
        for (int kb = 0; kb < 2; kb++)
            boff[t][kb] = ((kb * 16 + g8) << 8) + slot * 8;
    }

    const int aslot = ((lane ^ ((lane >> 3) & 3)) << 4);

    float acc[4][4][4];
#pragma unroll
    for (int mi = 0; mi < 4; mi++)
#pragma unroll
        for (int ni = 0; ni < 4; ni++)
#pragma unroll
            for (int r = 0; r < 4; r++) acc[mi][ni][r] = 0.f;

    const int NC = K / BK;

    // prologue: chunk 0 -> buffer 0
    {
        const uint4 av0 = *reinterpret_cast<const uint4*>(A + (size_t)(row0 + ar) * K + ac);
        const uint4 av1 = *reinterpret_cast<const uint4*>(A + (size_t)(row0 + 64 + ar) * K + ac);
        const uint32_t a0[4] = {av0.x, av0.y, av0.z, av0.w};
        const uint32_t a1[4] = {av1.x, av1.y, av1.z, av1.w};
#pragma unroll
        for (int j = 0; j < 4; j++) {
            *reinterpret_cast<uint32_t*>(Asm + aoff[j]) = a0[j];
            *reinterpret_cast<uint32_t*>(Asm + aoff[j] + 2048) = a1[j];
        }
        float wreg[2][4];
#pragma unroll
        for (int t = 0; t < 2; t++)
#pragma unroll
            for (int s = 0; s < 4; s++)
                wreg[t][s] = W[(size_t)(kq + s * 4) * N + col0 + nn + t * 64];
#pragma unroll
        for (int t = 0; t < 2; t++)
#pragma unroll
            for (int kb = 0; kb < 2; kb++) {
                uint2 u = {f2tf32(wreg[t][kb * 2 + 0]), f2tf32(wreg[t][kb * 2 + 1])};
                *reinterpret_cast<uint2*>(Bsm + boff[t][kb]) = u;
            }
    }
    __syncthreads();

    for (int c = 0; c < NC; c++) {
        const int buf = c & 1;
        const char* Ab = Asm + buf * 8192;
        const char* Bb = Bsm + buf * 8192;

        uint4 av0, av1;
        float wreg[2][4];
        if (c + 1 < NC) {
            const int k0 = (c + 1) * BK;
            av0 = *reinterpret_cast<const uint4*>(A + (size_t)(row0 + ar) * K + k0 + ac);
            av1 = *reinterpret_cast<const uint4*>(A + (size_t)(row0 + 64 + ar) * K + k0 + ac);
#pragma unroll
            for (int t = 0; t < 2; t++)
#pragma unroll
                for (int s = 0; s < 4; s++)
                    wreg[t][s] = W[(size_t)(k0 + kq + s * 4) * N + col0 + nn + t * 64];
        }

#pragma unroll
        for (int kb = 0; kb < 2; kb++) {
            const char* Abk = Ab + (kb << 12);
            const char* Bbk = Bb + (kb << 12);
            uint4 afr[4];
            uint2 bfr[4];
#pragma unroll
            for (int mi = 0; mi < 4; mi++)
                afr[mi] = *reinterpret_cast<const uint4*>(Abk + ((g16b + mi) << 9) + aslot);
#pragma unroll
            for (int ni = 0; ni < 4; ni++) {
                const int g8 = bg8 + ni;
                bfr[ni] = *reinterpret_cast<const uint2*>(Bbk + (g8 << 8) + ((lane ^ (g8 & 3)) << 3));
            }
#pragma unroll
            for (int mi = 0; mi < 4; mi++)
#pragma unroll
                for (int ni = 0; ni < 4; ni++)
                    mma_tf32(acc[mi][ni],
                             reinterpret_cast<const uint32_t*>(&afr[mi]),
                             reinterpret_cast<const uint32_t*>(&bfr[ni]));
        }

        if (c + 1 < NC) {
            char* An = Asm + (buf ^ 1) * 8192;
            char* Bn = Bsm + (buf ^ 1) * 8192;
            const uint32_t a0[4] = {av0.x, av0.y, av0.z, av0.w};
            const uint32_t a1[4] = {av1.x, av1.y, av1.z, av1.w};
#pragma unroll
            for (int j = 0; j < 4; j++) {
                *reinterpret_cast<uint32_t*>(An + aoff[j]) = a0[j];
                *reinterpret_cast<uint32_t*>(An + aoff[j] + 2048) = a1[j];
            }
#pragma unroll
            for (int t = 0; t < 2; t++)
#pragma unroll
                for (int kb = 0; kb < 2; kb++) {
                    uint2 u = {f2tf32(wreg[t][kb * 2 + 0]), f2tf32(wreg[t][kb * 2 + 1])};
                    *reinterpret_cast<uint2*>(Bn + boff[t][kb]) = u;
                }
            __syncthreads();
        }
    }

    // epilogue (bias hoisted)
    const int lg = lane >> 2, lt = lane & 3;
    float2 bias2[4];
#pragma unroll
    for (int ni = 0; ni < 4; ni++)
        bias2[ni] = *reinterpret_cast<const float2*>(bias + col0 + n0w + ni * 8 + lt * 2);
#pragma unroll
    for (int mi = 0; mi < 4; mi++) {
#pragma unroll
        for (int half = 0; half < 2; half++) {
            const int r = row0 + m0w + mi * 16 + lg + half * 8;
#pragma unroll
            for (int ni = 0; ni < 4; ni++) {
                const int cc = col0 + n0w + ni * 8 + lt * 2;
                float2 o;
                o.x = acc[mi][ni][half * 2 + 0] + bias2[ni].x;
                o.y = acc[mi][ni][half * 2 + 1] + bias2[ni].y;
                if (act == 1) {
                    o.x = 0.5f * o.x * (1.0f + erff(o.x * 0.70710678118654752f));
                    o.y = 0.5f * o.y * (1.0f + erff(o.y * 0.70710678118654752f));
                }
                if (res) {
                    const float2 rv = *reinterpret_cast<const float2*>(res + (size_t)r * N + cc);
                    o.x += rv.x; o.y += rv.y;
                }
                if (outtf) {
                    o.x = __uint_as_float(f2tf32(o.x));
                    o.y = __uint_as_float(f2tf32(o.y));
                }
                *reinterpret_cast<float2*>(C + (size_t)r * N + cc) = o;
            }
        }
    }
}

__global__ __launch_bounds__(256) void mmagemm_kernel(const uint32_t* __restrict__ A,
                                                      const float* __restrict__ W,
                                                      const float* __restrict__ bias,
                                                      const float* __restrict__ res,
                                                      float* __restrict__ C,
                                                      int M, int N, int K, int act, int outtf)
{
    gemm_body(A, W, bias, res, C, M, N, K, act, outtf);
}

// batched-z variant: z selects (W, bias, C) from device tables
__global__ __launch_bounds__(256) void mmagemm_z_kernel(const uint32_t* __restrict__ A,
                                                        int M, int N, int K)
{
    const int z = blockIdx.z;
    gemm_body(A, g_Wtab[z], g_btab[z], nullptr, g_Ctab[z], M, N, K, 0, 0);
}

// ---------------- LayerNorm v2: warp-per-row ----------------
__global__ __launch_bounds__(256) void ln_kernel(const float* __restrict__ x,
                                                 const float* __restrict__ g,
                                                 const float* __restrict__ b,
                                                 float* __restrict__ out)
{
    const int warp = threadIdx.x >> 5, lane = threadIdx.x & 31;
    const int row = blockIdx.x * 8 + warp;
    const float4* xr = reinterpret_cast<const float4*>(x + (size_t)row * D_);
    uint4* outr = reinterpret_cast<uint4*>(out + (size_t)row * D_);
    const float4* g4 = reinterpret_cast<const float4*>(g);
    const float4* b4 = reinterpret_cast<const float4*>(b);

    float4 v[8];
#pragma unroll
    for (int k = 0; k < 8; k++) v[k] = xr[k * 32 + lane];

    float s = 0.f, ss = 0.f;
#pragma unroll
    for (int k = 0; k < 8; k++) {
        s  += v[k].x + v[k].y + v[k].z + v[k].w;
        ss += v[k].x * v[k].x + v[k].y * v[k].y + v[k].z * v[k].z + v[k].w * v[k].w;
    }
    for (int off = 16; off; off >>= 1) {
        s  += __shfl_xor_sync(0xffffffffu, s, off);
        ss += __shfl_xor_sync(0xffffffffu, ss, off);
    }
    const float mu = s * (1.0f / D_);
    const float var = ss * (1.0f / D_) - mu * mu;
    const float rstd = rsqrtf(var + 1e-5f);

#pragma unroll
    for (int k = 0; k < 8; k++) {
        const float4 gv = g4[k * 32 + lane];
        const float4 bv = b4[k * 32 + lane];
        uint4 o;
        o.x = f2tf32((v[k].x - mu) * rstd * gv.x + bv.x);
        o.y = f2tf32((v[k].y - mu) * rstd * gv.y + bv.y);
        o.z = f2tf32((v[k].z - mu) * rstd * gv.z + bv.z);
        o.w = f2tf32((v[k].w - mu) * rstd * gv.w + bv.w);
        outr[k * 32 + lane] = o;
    }
}

// ====== sparse attention v5 (unchanged) ======
#define QB 64
#define KW 192
#define KP 68
#define VP 196
#define ATTN_T 512
#define ATTN_SMEM ((KW * KP + 64 * VP + 16 * 32) * 4)

__global__ __launch_bounds__(ATTN_T) void attn5_kernel(const float* __restrict__ Q,
                                                       const float* __restrict__ K,
                                                       const float* __restrict__ V,
                                                       const int* __restrict__ mask,
                                                       float* __restrict__ O)
{
    extern __shared__ float smattn[];
    float* Ks  = smattn;
    float* Vt  = smattn + KW * KP;
    float* psm = smattn + KW * KP + 64 * VP;

    const int qb0 = blockIdx.x * QB;
    const int h = blockIdx.y;
    const int b = blockIdx.z;
    const int tid = threadIdx.x;
    const int warp = tid >> 5, lane = tid & 31;
    const int base_row = qb0 - 128;

    for (int idx = tid; idx < KW * 64; idx += ATTN_T) {
        const int r = idx >> 6, d = idx & 63;
        const int j = base_row + r;
        float kv = 0.f, vv = 0.f;
        if (j >= 0) {
            const size_t g = ((size_t)(b * S_ + j)) * D_ + h * 64 + d;
            kv = K[g]; vv = V[g];
        }
        Ks[r * KP + d] = kv;
        Vt[d * VP + r] = vv;
    }
    __syncthreads();

    float* pb = psm + warp * 32;

#pragma unroll 1
    for (int qi = 0; qi < 4; qi++) {
        const int o_in_blk = warp * 4 + qi;
        const int i = qb0 + o_in_blk;
        const float4* q4 = reinterpret_cast<const float4*>(Q + ((size_t)(b * S_ + i)) * D_ + h * 64);
        float4 rq[16];
#pragma unroll
        for (int d = 0; d < 16; d++) rq[d] = __ldg(q4 + d);
        const int* mrow = mask + (size_t)i * S_;
        const int u0 = o_in_blk >> 5;

        float s_str = -INFINITY;
        {
            const int j = i - 256 - 128 * lane;
            if (j >= 0) {
                const float4* kr = reinterpret_cast<const float4*>(K + ((size_t)(b * S_ + j)) * D_ + h * 64);
                float dv = 0.f;
#pragma unroll
                for (int d = 0; d < 16; d++) {
                    const float4 kv = __ldg(kr + d);
                    dv = fmaf(rq[d].x, kv.x, dv);
                    dv = fmaf(rq[d].y, kv.y, dv);
                    dv = fmaf(rq[d].z, kv.z, dv);
                    dv = fmaf(rq[d].w, kv.w, dv);
                }
                s_str = dv * 0.125f;
                if (mrow[j] == 0) s_str = NEG_;
            }
        }

        float s_loc[5];
#pragma unroll
        for (int t = 0; t < 5; t++) {
            const int koff = (u0 + t) * 32;
            const int j = base_row + koff + lane;
            float s = -INFINITY;
            if (j >= 0 && j >= i - 128 && j <= i) {
                const float4* kr = reinterpret_cast<const float4*>(Ks + (koff + lane) * KP);
                float dv = 0.f;
#pragma unroll
                for (int d = 0; d < 16; d++) {
                    const float4 kv = kr[d];
                    dv = fmaf(rq[d].x, kv.x, dv);
                    dv = fmaf(rq[d].y, kv.y, dv);
                    dv = fmaf(rq[d].z, kv.z, dv);
                    dv = fmaf(rq[d].w, kv.w, dv);
                }
                s = dv * 0.125f;
                if (mrow[j] == 0) s = NEG_;
            }
            s_loc[t] = s;
        }

        float m = s_str;
#pragma unroll
        for (int t = 0; t < 5; t++) m = fmaxf(m, s_loc[t]);
        for (int off = 16; off; off >>= 1)
            m = fmaxf(m, __shfl_xor_sync(0xffffffffu, m, off));

        const float p_str = __expf(s_str - m);
        float p_loc[5];
        float l = p_str;
#pragma unroll
        for (int t = 0; t < 5; t++) { p_loc[t] = __expf(s_loc[t] - m); l += p_loc[t]; }
        for (int off = 16; off; off >>= 1)
            l += __shfl_xor_sync(0xffffffffu, l, off);

        float acc0 = 0.f, acc1 = 0.f;
#pragma unroll 1
        for (int t = 0; t < 5; t++) {
            const int koff = (u0 + t) * 32;
            __syncwarp();
            pb[lane] = p_loc[t];
            __syncwarp();
            const float4* pv4 = reinterpret_cast<const float4*>(pb);
            const float4* v0 = reinterpret_cast<const float4*>(Vt + lane * VP + koff);
            const float4* v1 = reinterpret_cast<const float4*>(Vt + (lane + 32) * VP + koff);
#pragma unroll
            for (int kk = 0; kk < 8; kk++) {
                const float4 pp = pv4[kk];
                const float4 va = v0[kk];
                const float4 vb = v1[kk];
                acc0 = fmaf(pp.x, va.x, acc0);
                acc0 = fmaf(pp.y, va.y, acc0);
                acc0 = fmaf(pp.z, va.z, acc0);
                acc0 = fmaf(pp.w, va.w, acc0);
                acc1 = fmaf(pp.x, vb.x, acc1);
                acc1 = fmaf(pp.y, vb.y, acc1);
                acc1 = fmaf(pp.z, vb.z, acc1);
                acc1 = fmaf(pp.w, vb.w, acc1);
            }
        }
        const int cnt = (i >= 256) ? (((i - 256) >> 7) + 1) : 0;
        for (int l2 = 0; l2 < cnt; l2++) {
            const float pv = __shfl_sync(0xffffffffu, p_str, l2);
            const int j2 = i - 256 - 128 * l2;
            const float* vr = V + ((size_t)(b * S_ + j2)) * D_ + h * 64;
            acc0 = fmaf(pv, __ldg(vr + lane), acc0);
            acc1 = fmaf(pv, __ldg(vr + lane + 32), acc1);
        }

        const float inv = 1.0f / l;
        float* orow = O + ((size_t)(b * S_ + i)) * D_ + h * 64;
        orow[lane]      = __uint_as_float(f2tf32(acc0 * inv));
        orow[lane + 32] = __uint_as_float(f2tf32(acc1 * inv));
    }
}

// ---------------- host launcher ----------------
extern "C" void kernel_launch(void* const* d_in, const int* in_sizes, int n_in,
                              void* d_out, int out_size)
{
    (void)in_sizes; (void)n_in; (void)out_size;
    const float* x    = (const float*)d_in[0];
    const int*   mask = (const int*)  d_in[1];
    const float* Wq = (const float*)d_in[2];  const float* bq = (const float*)d_in[3];
    const float* Wk = (const float*)d_in[4];  const float* bk = (const float*)d_in[5];
    const float* Wv = (const float*)d_in[6];  const float* bv = (const float*)d_in[7];
    const float* Wo = (const float*)d_in[8];  const float* bo = (const float*)d_in[9];
    const float* W1 = (const float*)d_in[10]; const float* bf1 = (const float*)d_in[11];
    const float* W2 = (const float*)d_in[12]; const float* bf2 = (const float*)d_in[13];
    const float* g1 = (const float*)d_in[14]; const float* bl1 = (const float*)d_in[15];
    const float* g2 = (const float*)d_in[16]; const float* bl2 = (const float*)d_in[17];
    float* out = (float*)d_out;

    float *n1, *q, *k, *v, *o, *x1, *n2, *ff;
    cudaGetSymbolAddress((void**)&n1, g_n1);
    cudaGetSymbolAddress((void**)&q,  g_q);
    cudaGetSymbolAddress((void**)&k,  g_k);
    cudaGetSymbolAddress((void**)&v,  g_v);
    cudaGetSymbolAddress((void**)&o,  g_o);
    cudaGetSymbolAddress((void**)&x1, g_x1);
    cudaGetSymbolAddress((void**)&n2, g_n2);
    cudaGetSymbolAddress((void**)&ff, g_ff);

    cudaFuncSetAttribute(attn5_kernel, cudaFuncAttributeMaxDynamicSharedMemorySize, ATTN_SMEM);

    const int M = B_ * S_;  // 4096

    // 0) pointer tables for batched QKV
    set_tabs_kernel<<<1, 1>>>(Wq, Wk, Wv, bq, bk, bv, q, k, v);

    // 1) LN1 -> n1 (tf32)
    ln_kernel<<<M / 8, 256>>>(x, g1, bl1, n1);

    // 2) fused-z QKV projections (one launch, 768 CTAs)
    {
        dim3 grid(D_ / BN, M / BM, 3);
        mmagemm_z_kernel<<<grid, 256>>>((const uint32_t*)n1, M, D_, D_);
    }

    // 3) sparse attention -> o (tf32)
    {
        dim3 grid(S_ / QB, H_, B_);
        attn5_kernel<<<grid, ATTN_T, ATTN_SMEM>>>(q, k, v, mask, o);
    }

    // 4) output projection + residual -> x1 (fp32)
    {
        dim3 grid(D_ / BN, M / BM);
        mmagemm_kernel<<<grid, 256>>>((const uint32_t*)o, Wo, bo, x, x1, M, D_, D_, 0, 0);
    }

    // 5) LN2 -> n2 (tf32)
    ln_kernel<<<M / 8, 256>>>(x1, g2, bl2, n2);

    // 6) FFN up + GELU -> ff (tf32)
    {
        dim3 grid(FF_ / BN, M / BM);
        mmagemm_kernel<<<grid, 256>>>((const uint32_t*)n2, W1, bf1, nullptr, ff, M, FF_, D_, 1, 1);
    }

    // 7) FFN down + residual -> out (fp32)
    {
        dim3 grid(D_ / BN, M / BM);
        mmagemm_kernel<<<grid, 256>>>((const uint32_t*)ff, W2, bf2, x1, out, M, D_, FF_, 0, 0);
    }
}